// round 1
// baseline (speedup 1.0000x reference)
#include <cuda_runtime.h>
#include <math.h>

#define N_NODES 50000
#define N_EDGES 800000
#define IN_DIM  384
#define HID     128
#define HEADS   4
#define OUT_DIM 5
#define F1      (HEADS * HID)   /* 512 */
#define EPS     1e-16f
#define NEG_SLOPE 0.2f

/* ---------------- scratch (device globals; no allocations allowed) -------- */
__device__ float g_h1  [(size_t)N_NODES * F1];     /* x @ W1          102.4MB */
__device__ float g_out1[(size_t)N_NODES * F1];     /* agg -> elu(x2)  102.4MB */
__device__ float g_alS1[N_NODES * HEADS];
__device__ float g_alD1[N_NODES * HEADS];
__device__ float g_m1  [N_NODES * HEADS];
__device__ float g_den1[N_NODES * HEADS];
__device__ float g_e1  [(size_t)N_EDGES * HEADS];  /* 12.8MB */
__device__ float g_h2  [N_NODES * OUT_DIM];
__device__ float g_alS2[N_NODES];
__device__ float g_alD2[N_NODES];
__device__ float g_m2  [N_NODES];
__device__ float g_den2[N_NODES];
__device__ float g_e2  [N_EDGES];

/* ---------------- helpers ------------------------------------------------- */
__device__ __forceinline__ float atomicMaxFloat(float* addr, float value) {
    if (value >= 0.0f)
        return __int_as_float(atomicMax((int*)addr, __float_as_int(value)));
    else
        return __uint_as_float(atomicMin((unsigned int*)addr, __float_as_uint(value)));
}

__device__ __forceinline__ float leaky(float v) {
    return v > 0.0f ? v : NEG_SLOPE * v;
}

/* ---------------- init: zeros + (-inf) for segment-max -------------------- */
__global__ void init_kernel(float* __restrict__ dout) {
    const float NEG_INF = __int_as_float(0xff800000);
    size_t t = (size_t)blockIdx.x * blockDim.x + threadIdx.x;
    if (t < (size_t)N_NODES * F1) g_out1[t] = 0.0f;
    if (t < (size_t)N_NODES * HEADS) { g_m1[t] = NEG_INF; g_den1[t] = 0.0f; }
    if (t < (size_t)N_NODES) { g_m2[t] = NEG_INF; g_den2[t] = 0.0f; }
    if (t < (size_t)N_NODES * OUT_DIM) dout[t] = 0.0f;
}

/* ---------------- GEMM1: h1 = x[ M,384 ] @ W1[384,512] -------------------- */
#define BM 128
#define BN 64
#define BK 16

__global__ __launch_bounds__(256)
void gemm1_kernel(const float* __restrict__ A, const float* __restrict__ B) {
    __shared__ __align__(16) float As[BM][BK];
    __shared__ __align__(16) float Bs[BK][BN];

    const int tx = threadIdx.x & 15;        /* 0..15 -> col group of 4 */
    const int ty = threadIdx.x >> 4;        /* 0..15 -> row group of 8 */
    const int bx = blockIdx.x;              /* 0..7   (512/64)         */
    const int by = blockIdx.y;              /* 0..390 (50000/128)      */
    const int row_base = by * BM;

    float acc[8][4];
#pragma unroll
    for (int i = 0; i < 8; i++)
#pragma unroll
        for (int j = 0; j < 4; j++) acc[i][j] = 0.0f;

    for (int k0 = 0; k0 < IN_DIM; k0 += BK) {
        /* load A tile: 128x16 = 512 float4, 2 per thread */
#pragma unroll
        for (int l = 0; l < 2; l++) {
            int idx = threadIdx.x + l * 256;
            int r  = idx >> 2;
            int c4 = idx & 3;
            int gr = row_base + r;
            float4 v = make_float4(0.f, 0.f, 0.f, 0.f);
            if (gr < N_NODES)
                v = *(const float4*)&A[(size_t)gr * IN_DIM + k0 + c4 * 4];
            *(float4*)&As[r][c4 * 4] = v;
        }
        /* load B tile: 16x64 = 256 float4, 1 per thread */
        {
            int r  = threadIdx.x >> 4;
            int c4 = threadIdx.x & 15;
            float4 v = *(const float4*)&B[(size_t)(k0 + r) * F1 + bx * BN + c4 * 4];
            *(float4*)&Bs[r][c4 * 4] = v;
        }
        __syncthreads();

#pragma unroll
        for (int kk = 0; kk < BK; kk++) {
            float4 b4 = *(const float4*)&Bs[kk][tx * 4];
#pragma unroll
            for (int i = 0; i < 8; i++) {
                float av = As[ty * 8 + i][kk];
                acc[i][0] += av * b4.x;
                acc[i][1] += av * b4.y;
                acc[i][2] += av * b4.z;
                acc[i][3] += av * b4.w;
            }
        }
        __syncthreads();
    }

#pragma unroll
    for (int i = 0; i < 8; i++) {
        int gr = row_base + ty * 8 + i;
        if (gr < N_NODES) {
            float4 v = make_float4(acc[i][0], acc[i][1], acc[i][2], acc[i][3]);
            *(float4*)&g_h1[(size_t)gr * F1 + bx * BN + tx * 4] = v;
        }
    }
}

/* ---------------- alpha1: per-node attention logits ----------------------- */
__global__ void alpha1_kernel(const float* __restrict__ a_src,
                              const float* __restrict__ a_dst) {
    int w = (blockIdx.x * blockDim.x + threadIdx.x) >> 5;
    int lane = threadIdx.x & 31;
    if (w >= N_NODES) return;
    const float* row = g_h1 + (size_t)w * F1;
    float s[HEADS] = {0, 0, 0, 0}, d[HEADS] = {0, 0, 0, 0};
    for (int c = lane; c < F1; c += 32) {
        float v = row[c];
        int hh = c >> 7;
        s[hh] += v * a_src[c];   /* a_src flattened [H,HID] == [512] */
        d[hh] += v * a_dst[c];
    }
#pragma unroll
    for (int hh = 0; hh < HEADS; hh++) {
        float vs = s[hh], vd = d[hh];
#pragma unroll
        for (int o = 16; o; o >>= 1) {
            vs += __shfl_xor_sync(0xffffffffu, vs, o);
            vd += __shfl_xor_sync(0xffffffffu, vd, o);
        }
        if (lane == 0) { g_alS1[w * HEADS + hh] = vs; g_alD1[w * HEADS + hh] = vd; }
    }
}

/* ---------------- layer1 edge pass A: logits + segment max ---------------- */
__global__ void edge_max1(const int* __restrict__ src, const int* __restrict__ dst) {
    int t = blockIdx.x * blockDim.x + threadIdx.x;
    if (t >= N_EDGES * HEADS) return;
    int e = t >> 2, h = t & 3;
    int s = src[e], d = dst[e];
    float v = leaky(g_alS1[s * HEADS + h] + g_alD1[d * HEADS + h]);
    g_e1[t] = v;
    atomicMaxFloat(&g_m1[d * HEADS + h], v);
}

/* -------- layer1 edge pass B: exp, denom, weighted aggregate (fused) ------ */
__global__ __launch_bounds__(256)
void edge_agg1(const int* __restrict__ src, const int* __restrict__ dst) {
    int gw = (blockIdx.x * blockDim.x + threadIdx.x) >> 5;
    int lane = threadIdx.x & 31;
    if (gw >= N_EDGES * HEADS) return;
    int e = gw >> 2, h = gw & 3;
    int s = src[e], d = dst[e];
    float ex = 0.0f;
    if (lane == 0) {
        ex = __expf(g_e1[gw] - g_m1[d * HEADS + h]);
        atomicAdd(&g_den1[d * HEADS + h], ex);
    }
    ex = __shfl_sync(0xffffffffu, ex, 0);
    const float4* hv = (const float4*)g_h1;
    float4 v = hv[(size_t)s * (F1 / 4) + h * 32 + lane];
    float* o = g_out1 + (size_t)d * F1 + h * HID + lane * 4;
    atomicAdd(o + 0, ex * v.x);
    atomicAdd(o + 1, ex * v.y);
    atomicAdd(o + 2, ex * v.z);
    atomicAdd(o + 3, ex * v.w);
}

/* -------- layer1 node epilogue: normalize, +bias, elu --------------------- */
__global__ void node1_kernel(const float* __restrict__ b1) {
    size_t t = (size_t)blockIdx.x * blockDim.x + threadIdx.x;
    if (t >= (size_t)N_NODES * F1) return;
    int c = (int)(t & (F1 - 1));
    int n = (int)(t >> 9);
    float v = g_out1[t] / (g_den1[n * HEADS + (c >> 7)] + EPS) + b1[c];
    g_out1[t] = v > 0.0f ? v : expm1f(v);   /* elu, in place -> x2 */
}

/* -------- layer2: per-node GEMV (512 -> 5) + alpha2 ----------------------- */
__global__ void layer2_node(const float* __restrict__ W2,
                            const float* __restrict__ a_s,
                            const float* __restrict__ a_d) {
    int w = (blockIdx.x * blockDim.x + threadIdx.x) >> 5;
    int lane = threadIdx.x & 31;
    if (w >= N_NODES) return;
    const float* row = g_out1 + (size_t)w * F1;
    float acc[OUT_DIM] = {0, 0, 0, 0, 0};
    for (int c = lane; c < F1; c += 32) {
        float xv = row[c];
        const float* wr = W2 + c * OUT_DIM;
#pragma unroll
        for (int k = 0; k < OUT_DIM; k++) acc[k] += xv * wr[k];
    }
#pragma unroll
    for (int k = 0; k < OUT_DIM; k++) {
#pragma unroll
        for (int o = 16; o; o >>= 1)
            acc[k] += __shfl_xor_sync(0xffffffffu, acc[k], o);
    }
    if (lane == 0) {
        float as = 0.0f, ad = 0.0f;
#pragma unroll
        for (int k = 0; k < OUT_DIM; k++) {
            g_h2[w * OUT_DIM + k] = acc[k];
            as += acc[k] * a_s[k];
            ad += acc[k] * a_d[k];
        }
        g_alS2[w] = as;
        g_alD2[w] = ad;
    }
}

/* -------- layer2 edge pass A ---------------------------------------------- */
__global__ void edge_max2(const int* __restrict__ src, const int* __restrict__ dst) {
    int e = blockIdx.x * blockDim.x + threadIdx.x;
    if (e >= N_EDGES) return;
    int s = src[e], d = dst[e];
    float v = leaky(g_alS2[s] + g_alD2[d]);
    g_e2[e] = v;
    atomicMaxFloat(&g_m2[d], v);
}

/* -------- layer2 edge pass B (fused exp/denom/aggregate) ------------------ */
__global__ void edge_agg2(const int* __restrict__ src, const int* __restrict__ dst,
                          float* __restrict__ dout) {
    int e = blockIdx.x * blockDim.x + threadIdx.x;
    if (e >= N_EDGES) return;
    int s = src[e], d = dst[e];
    float ex = __expf(g_e2[e] - g_m2[d]);
    atomicAdd(&g_den2[d], ex);
    const float* hs = g_h2 + s * OUT_DIM;
    float* o = dout + d * OUT_DIM;
#pragma unroll
    for (int k = 0; k < OUT_DIM; k++) atomicAdd(o + k, ex * hs[k]);
}

/* -------- final epilogue --------------------------------------------------- */
__global__ void final_kernel(float* __restrict__ dout, const float* __restrict__ b2) {
    int t = blockIdx.x * blockDim.x + threadIdx.x;
    if (t >= N_NODES * OUT_DIM) return;
    int n = t / OUT_DIM;
    int k = t - n * OUT_DIM;
    dout[t] = dout[t] / (g_den2[n] + EPS) + b2[k];
}

/* ---------------- launch --------------------------------------------------- */
extern "C" void kernel_launch(void* const* d_in, const int* in_sizes, int n_in,
                              void* d_out, int out_size) {
    const float* x     = (const float*)d_in[0];
    const int*   ei    = (const int*)  d_in[1];
    const float* W1    = (const float*)d_in[2];
    const float* aS1   = (const float*)d_in[3];
    const float* aD1   = (const float*)d_in[4];
    const float* b1    = (const float*)d_in[5];
    const float* W2    = (const float*)d_in[6];
    const float* aS2   = (const float*)d_in[7];
    const float* aD2   = (const float*)d_in[8];
    const float* b2    = (const float*)d_in[9];
    float*       out   = (float*)d_out;

    const int* src = ei;
    const int* dst = ei + N_EDGES;

    /* init scratch + output */
    {
        size_t n = (size_t)N_NODES * F1;
        init_kernel<<<(unsigned)((n + 255) / 256), 256>>>(out);
    }

    /* layer 1 */
    gemm1_kernel<<<dim3(F1 / BN, (N_NODES + BM - 1) / BM), 256>>>(x, W1);
    alpha1_kernel<<<(N_NODES * 32 + 255) / 256, 256>>>(aS1, aD1);
    edge_max1<<<(N_EDGES * HEADS + 255) / 256, 256>>>(src, dst);
    {
        long long threads = (long long)N_EDGES * HEADS * 32;
        edge_agg1<<<(unsigned)((threads + 255) / 256), 256>>>(src, dst);
    }
    node1_kernel<<<(unsigned)(((size_t)N_NODES * F1 + 255) / 256), 256>>>(b1);

    /* layer 2 */
    layer2_node<<<(N_NODES * 32 + 255) / 256, 256>>>(W2, aS2, aD2);
    edge_max2<<<(N_EDGES + 255) / 256, 256>>>(src, dst);
    edge_agg2<<<(N_EDGES + 255) / 256, 256>>>(src, dst, out);
    final_kernel<<<(N_NODES * OUT_DIM + 255) / 256, 256>>>(out, b2);
}

// round 2
// speedup vs baseline: 1.3293x; 1.3293x over previous
#include <cuda_runtime.h>
#include <math.h>

#define N_NODES 50000
#define N_EDGES 800000
#define IN_DIM  384
#define HID     128
#define HEADS   4
#define OUT_DIM 5
#define F1      (HEADS * HID)   /* 512 */
#define EPS     1e-16f
#define NEG_SLOPE 0.2f

/* ---------------- scratch (device globals; no allocations allowed) -------- */
__device__ float g_h1  [(size_t)N_NODES * F1];     /* x @ W1          102.4MB */
__device__ float g_out1[(size_t)N_NODES * F1];     /* agg -> elu(x2)  102.4MB */
__device__ float g_alS1[N_NODES * HEADS];
__device__ float g_alD1[N_NODES * HEADS];
__device__ float g_m1  [N_NODES * HEADS];
__device__ float g_den1[N_NODES * HEADS];
__device__ float g_e1  [(size_t)N_EDGES * HEADS];  /* 12.8MB */
__device__ float g_h2p [N_NODES * 8];              /* padded [N,8], 5 used */
__device__ float g_out2[N_NODES * 8];              /* padded accum target   */
__device__ float g_alS2[N_NODES];
__device__ float g_alD2[N_NODES];
__device__ float g_m2  [N_NODES];
__device__ float g_den2[N_NODES];
__device__ float g_e2  [N_EDGES];

/* ---------------- helpers ------------------------------------------------- */
__device__ __forceinline__ void atomicMaxFloat(float* addr, float value) {
    if (value >= 0.0f)
        atomicMax((int*)addr, __float_as_int(value));
    else
        atomicMin((unsigned int*)addr, __float_as_uint(value));
}

__device__ __forceinline__ void red_add_v4(float* addr, float a, float b,
                                           float c, float d) {
    asm volatile("red.global.add.v4.f32 [%0], {%1,%2,%3,%4};"
                 :: "l"(addr), "f"(a), "f"(b), "f"(c), "f"(d) : "memory");
}

__device__ __forceinline__ float leaky(float v) {
    return v > 0.0f ? v : NEG_SLOPE * v;
}

/* ---------------- init: zeros + (-inf) for segment-max -------------------- */
__global__ void init_kernel() {
    const float NEG_INF = __int_as_float(0xff800000);
    size_t t = (size_t)blockIdx.x * blockDim.x + threadIdx.x;
    if (t < (size_t)N_NODES * F1) g_out1[t] = 0.0f;
    if (t < (size_t)N_NODES * 8) g_out2[t] = 0.0f;
    if (t < (size_t)N_NODES * HEADS) { g_m1[t] = NEG_INF; g_den1[t] = 0.0f; }
    if (t < (size_t)N_NODES) { g_m2[t] = NEG_INF; g_den2[t] = 0.0f; }
}

/* ---------------- GEMM1: h1 = x[M,384] @ W1[384,512] ---------------------- */
#define GBM 128
#define GBN 128
#define GBK 8

__global__ __launch_bounds__(256)
void gemm1_kernel(const float* __restrict__ A, const float* __restrict__ B) {
    __shared__ __align__(16) float As[2][GBK][GBM];
    __shared__ __align__(16) float Bs[2][GBK][GBN];

    const int tid = threadIdx.x;
    const int tx = tid & 15;                /* 0..15: col group */
    const int ty = tid >> 4;                /* 0..15: row group */
    const int bn = blockIdx.x * GBN;
    const int bm = blockIdx.y * GBM;

    /* global load assignments */
    const int a_row  = tid >> 1;            /* 0..127 */
    const int a_kcol = (tid & 1) * 4;       /* 0 or 4 */
    const int b_krow = tid >> 5;            /* 0..7   */
    const int b_col  = (tid & 31) * 4;      /* 0..124 */

    float acc[8][8];
#pragma unroll
    for (int i = 0; i < 8; i++)
#pragma unroll
        for (int j = 0; j < 8; j++) acc[i][j] = 0.0f;

    const int a_gr = bm + a_row;

    float4 a_reg, b_reg;
    a_reg = (a_gr < N_NODES) ? *(const float4*)&A[(size_t)a_gr * IN_DIM + a_kcol]
                             : make_float4(0.f, 0.f, 0.f, 0.f);
    b_reg = *(const float4*)&B[(size_t)b_krow * F1 + bn + b_col];

    As[0][a_kcol + 0][a_row] = a_reg.x;
    As[0][a_kcol + 1][a_row] = a_reg.y;
    As[0][a_kcol + 2][a_row] = a_reg.z;
    As[0][a_kcol + 3][a_row] = a_reg.w;
    *(float4*)&Bs[0][b_krow][b_col] = b_reg;
    __syncthreads();

    int buf = 0;
    for (int k0 = 0; k0 < IN_DIM; k0 += GBK) {
        const int nk = k0 + GBK;
        if (nk < IN_DIM) {
            a_reg = (a_gr < N_NODES)
                    ? *(const float4*)&A[(size_t)a_gr * IN_DIM + nk + a_kcol]
                    : make_float4(0.f, 0.f, 0.f, 0.f);
            b_reg = *(const float4*)&B[(size_t)(nk + b_krow) * F1 + bn + b_col];
        }
#pragma unroll
        for (int kk = 0; kk < GBK; kk++) {
            float4 a0 = *(const float4*)&As[buf][kk][ty * 4];
            float4 a1 = *(const float4*)&As[buf][kk][ty * 4 + 64];
            float4 b0 = *(const float4*)&Bs[buf][kk][tx * 4];
            float4 b1 = *(const float4*)&Bs[buf][kk][tx * 4 + 64];
            float av[8] = {a0.x, a0.y, a0.z, a0.w, a1.x, a1.y, a1.z, a1.w};
            float bv[8] = {b0.x, b0.y, b0.z, b0.w, b1.x, b1.y, b1.z, b1.w};
#pragma unroll
            for (int i = 0; i < 8; i++)
#pragma unroll
                for (int j = 0; j < 8; j++)
                    acc[i][j] += av[i] * bv[j];
        }
        if (nk < IN_DIM) {
            const int nb = buf ^ 1;
            As[nb][a_kcol + 0][a_row] = a_reg.x;
            As[nb][a_kcol + 1][a_row] = a_reg.y;
            As[nb][a_kcol + 2][a_row] = a_reg.z;
            As[nb][a_kcol + 3][a_row] = a_reg.w;
            *(float4*)&Bs[nb][b_krow][b_col] = b_reg;
            __syncthreads();
            buf = nb;
        }
    }

#pragma unroll
    for (int i = 0; i < 8; i++) {
        int gr = bm + ty * 4 + (i < 4 ? i : 60 + i);  /* ty*4+i or ty*4+64+(i-4) */
        if (gr < N_NODES) {
            float4 v0 = make_float4(acc[i][0], acc[i][1], acc[i][2], acc[i][3]);
            float4 v1 = make_float4(acc[i][4], acc[i][5], acc[i][6], acc[i][7]);
            *(float4*)&g_h1[(size_t)gr * F1 + bn + tx * 4]      = v0;
            *(float4*)&g_h1[(size_t)gr * F1 + bn + tx * 4 + 64] = v1;
        }
    }
}

/* ---------------- alpha1: per-node attention logits ----------------------- */
__global__ void alpha1_kernel(const float* __restrict__ a_src,
                              const float* __restrict__ a_dst) {
    int w = (blockIdx.x * blockDim.x + threadIdx.x) >> 5;
    int lane = threadIdx.x & 31;
    if (w >= N_NODES) return;
    const float* row = g_h1 + (size_t)w * F1;
    float s[HEADS] = {0, 0, 0, 0}, d[HEADS] = {0, 0, 0, 0};
    for (int c = lane; c < F1; c += 32) {
        float v = row[c];
        int hh = c >> 7;
        s[hh] += v * a_src[c];
        d[hh] += v * a_dst[c];
    }
#pragma unroll
    for (int hh = 0; hh < HEADS; hh++) {
        float vs = s[hh], vd = d[hh];
#pragma unroll
        for (int o = 16; o; o >>= 1) {
            vs += __shfl_xor_sync(0xffffffffu, vs, o);
            vd += __shfl_xor_sync(0xffffffffu, vd, o);
        }
        if (lane == 0) { g_alS1[w * HEADS + hh] = vs; g_alD1[w * HEADS + hh] = vd; }
    }
}

/* ---------------- layer1 edge pass A: logits + segment max ---------------- */
__global__ void edge_max1(const int* __restrict__ src, const int* __restrict__ dst) {
    int t = blockIdx.x * blockDim.x + threadIdx.x;
    if (t >= N_EDGES * HEADS) return;
    int e = t >> 2, h = t & 3;
    int s = src[e], d = dst[e];
    float v = leaky(g_alS1[s * HEADS + h] + g_alD1[d * HEADS + h]);
    g_e1[t] = v;
    atomicMaxFloat(&g_m1[d * HEADS + h], v);
}

/* -------- layer1 edge pass B: exp, denom, weighted aggregate (fused) ------ */
__global__ __launch_bounds__(256)
void edge_agg1(const int* __restrict__ src, const int* __restrict__ dst) {
    int gw = (blockIdx.x * blockDim.x + threadIdx.x) >> 5;
    int lane = threadIdx.x & 31;
    if (gw >= N_EDGES * HEADS) return;
    int e = gw >> 2, h = gw & 3;
    int s = src[e], d = dst[e];
    float ex = 0.0f;
    if (lane == 0) {
        ex = __expf(g_e1[gw] - g_m1[d * HEADS + h]);
        atomicAdd(&g_den1[d * HEADS + h], ex);
    }
    ex = __shfl_sync(0xffffffffu, ex, 0);
    const float4* hv = (const float4*)g_h1;
    float4 v = hv[(size_t)s * (F1 / 4) + h * 32 + lane];
    float* o = g_out1 + (size_t)d * F1 + h * HID + lane * 4;
    red_add_v4(o, ex * v.x, ex * v.y, ex * v.z, ex * v.w);
}

/* -------- layer1 node epilogue: normalize, +bias, elu --------------------- */
__global__ void node1_kernel(const float* __restrict__ b1) {
    size_t t = (size_t)blockIdx.x * blockDim.x + threadIdx.x;
    if (t >= (size_t)N_NODES * F1) return;
    int c = (int)(t & (F1 - 1));
    int n = (int)(t >> 9);
    float v = g_out1[t] / (g_den1[n * HEADS + (c >> 7)] + EPS) + b1[c];
    g_out1[t] = v > 0.0f ? v : expm1f(v);   /* elu, in place -> x2 */
}

/* -------- layer2: per-node GEMV (512 -> 5) + alpha2 ----------------------- */
__global__ void layer2_node(const float* __restrict__ W2,
                            const float* __restrict__ a_s,
                            const float* __restrict__ a_d) {
    int w = (blockIdx.x * blockDim.x + threadIdx.x) >> 5;
    int lane = threadIdx.x & 31;
    if (w >= N_NODES) return;
    const float* row = g_out1 + (size_t)w * F1;
    float acc[OUT_DIM] = {0, 0, 0, 0, 0};
    for (int c = lane; c < F1; c += 32) {
        float xv = row[c];
        const float* wr = W2 + c * OUT_DIM;
#pragma unroll
        for (int k = 0; k < OUT_DIM; k++) acc[k] += xv * wr[k];
    }
#pragma unroll
    for (int k = 0; k < OUT_DIM; k++) {
#pragma unroll
        for (int o = 16; o; o >>= 1)
            acc[k] += __shfl_xor_sync(0xffffffffu, acc[k], o);
    }
    if (lane == 0) {
        float as = 0.0f, ad = 0.0f;
#pragma unroll
        for (int k = 0; k < OUT_DIM; k++) {
            g_h2p[w * 8 + k] = acc[k];
            as += acc[k] * a_s[k];
            ad += acc[k] * a_d[k];
        }
        g_alS2[w] = as;
        g_alD2[w] = ad;
    }
}

/* -------- layer2 edge pass A ---------------------------------------------- */
__global__ void edge_max2(const int* __restrict__ src, const int* __restrict__ dst) {
    int e = blockIdx.x * blockDim.x + threadIdx.x;
    if (e >= N_EDGES) return;
    int s = src[e], d = dst[e];
    float v = leaky(g_alS2[s] + g_alD2[d]);
    g_e2[e] = v;
    atomicMaxFloat(&g_m2[d], v);
}

/* -------- layer2 edge pass B (fused exp/denom/aggregate) ------------------ */
__global__ void edge_agg2(const int* __restrict__ src, const int* __restrict__ dst) {
    int e = blockIdx.x * blockDim.x + threadIdx.x;
    if (e >= N_EDGES) return;
    int s = src[e], d = dst[e];
    float ex = __expf(g_e2[e] - g_m2[d]);
    atomicAdd(&g_den2[d], ex);
    const float4* h4 = (const float4*)&g_h2p[s * 8];
    float4 v = h4[0];
    float  v4 = g_h2p[s * 8 + 4];
    float* o = &g_out2[d * 8];
    red_add_v4(o, ex * v.x, ex * v.y, ex * v.z, ex * v.w);
    atomicAdd(o + 4, ex * v4);
}

/* -------- final epilogue --------------------------------------------------- */
__global__ void final_kernel(float* __restrict__ dout, const float* __restrict__ b2) {
    int t = blockIdx.x * blockDim.x + threadIdx.x;
    if (t >= N_NODES * OUT_DIM) return;
    int n = t / OUT_DIM;
    int k = t - n * OUT_DIM;
    dout[t] = g_out2[n * 8 + k] / (g_den2[n] + EPS) + b2[k];
}

/* ---------------- launch --------------------------------------------------- */
extern "C" void kernel_launch(void* const* d_in, const int* in_sizes, int n_in,
                              void* d_out, int out_size) {
    const float* x     = (const float*)d_in[0];
    const int*   ei    = (const int*)  d_in[1];
    const float* W1    = (const float*)d_in[2];
    const float* aS1   = (const float*)d_in[3];
    const float* aD1   = (const float*)d_in[4];
    const float* b1    = (const float*)d_in[5];
    const float* W2    = (const float*)d_in[6];
    const float* aS2   = (const float*)d_in[7];
    const float* aD2   = (const float*)d_in[8];
    const float* b2    = (const float*)d_in[9];
    float*       out   = (float*)d_out;

    const int* src = ei;
    const int* dst = ei + N_EDGES;

    /* init scratch */
    {
        size_t n = (size_t)N_NODES * F1;
        init_kernel<<<(unsigned)((n + 255) / 256), 256>>>();
    }

    /* layer 1 */
    gemm1_kernel<<<dim3(F1 / GBN, (N_NODES + GBM - 1) / GBM), 256>>>(x, W1);
    alpha1_kernel<<<(N_NODES * 32 + 255) / 256, 256>>>(aS1, aD1);
    edge_max1<<<(N_EDGES * HEADS + 255) / 256, 256>>>(src, dst);
    {
        long long threads = (long long)N_EDGES * HEADS * 32;
        edge_agg1<<<(unsigned)((threads + 255) / 256), 256>>>(src, dst);
    }
    node1_kernel<<<(unsigned)(((size_t)N_NODES * F1 + 255) / 256), 256>>>(b1);

    /* layer 2 */
    layer2_node<<<(N_NODES * 32 + 255) / 256, 256>>>(W2, aS2, aD2);
    edge_max2<<<(N_EDGES + 255) / 256, 256>>>(src, dst);
    edge_agg2<<<(N_EDGES + 255) / 256, 256>>>(src, dst);
    final_kernel<<<(N_NODES * OUT_DIM + 255) / 256, 256>>>(out, b2);
}

// round 4
// speedup vs baseline: 1.6548x; 1.2449x over previous
#include <cuda_runtime.h>
#include <cuda_bf16.h>
#include <math.h>
#include <stdint.h>

#define N_NODES 50000
#define N_PAD   50048            /* 391 * 128 */
#define N_EDGES 800000
#define IN_DIM  384
#define HID     128
#define HEADS   4
#define OUT_DIM 5
#define F1      (HEADS * HID)    /* 512 */
#define EPS     1e-16f
#define NEG_SLOPE 0.2f
#define KC      64               /* K per chunk */
#define NCHUNK  18               /* 3 terms * 384/64 */

/* ---------------- scratch (device globals; no allocations allowed) -------- */
__device__ float g_h1  [(size_t)N_NODES * F1];
__device__ float g_out1[(size_t)N_NODES * F1];
__device__ float g_alS1[N_NODES * HEADS];
__device__ float g_alD1[N_NODES * HEADS];
__device__ float g_m1  [N_NODES * HEADS];
__device__ float g_den1[N_NODES * HEADS];
__device__ float g_e1  [(size_t)N_EDGES * HEADS];
__device__ float g_h2p [N_NODES * 8];
__device__ float g_out2[N_NODES * 8];
__device__ float g_alS2[N_NODES];
__device__ float g_alD2[N_NODES];
__device__ float g_m2  [N_NODES];
__device__ float g_den2[N_NODES];
__device__ float g_e2  [N_EDGES];
/* bf16 split operands for tensor-core GEMM1 */
__device__ __nv_bfloat16 g_xhi[(size_t)N_PAD * IN_DIM];
__device__ __nv_bfloat16 g_xlo[(size_t)N_PAD * IN_DIM];
__device__ __nv_bfloat16 g_wthi[(size_t)F1 * IN_DIM];   /* W1^T [512 x 384] */
__device__ __nv_bfloat16 g_wtlo[(size_t)F1 * IN_DIM];

/* ---------------- helpers ------------------------------------------------- */
__device__ __forceinline__ uint32_t smem_u32(const void* p) {
    uint32_t a;
    asm("{ .reg .u64 t; cvta.to.shared.u64 t, %1; cvt.u32.u64 %0, t; }"
        : "=r"(a) : "l"(p));
    return a;
}
__device__ __forceinline__ void atomicMaxFloat(float* addr, float value) {
    if (value >= 0.0f) atomicMax((int*)addr, __float_as_int(value));
    else               atomicMin((unsigned int*)addr, __float_as_uint(value));
}
__device__ __forceinline__ void red_add_v4(float* addr, float a, float b,
                                           float c, float d) {
    asm volatile("red.global.add.v4.f32 [%0], {%1,%2,%3,%4};"
                 :: "l"(addr), "f"(a), "f"(b), "f"(c), "f"(d) : "memory");
}
__device__ __forceinline__ float leaky(float v) {
    return v > 0.0f ? v : NEG_SLOPE * v;
}
__device__ __forceinline__ void ldsm_x4(uint32_t* r, uint32_t addr) {
    asm volatile("ldmatrix.sync.aligned.m8n8.x4.shared.b16 {%0,%1,%2,%3}, [%4];"
                 : "=r"(r[0]), "=r"(r[1]), "=r"(r[2]), "=r"(r[3]) : "r"(addr));
}
__device__ __forceinline__ void ldsm_x2(uint32_t* r, uint32_t addr) {
    asm volatile("ldmatrix.sync.aligned.m8n8.x2.shared.b16 {%0,%1}, [%2];"
                 : "=r"(r[0]), "=r"(r[1]) : "r"(addr));
}
__device__ __forceinline__ void mma_bf16(float* c, const uint32_t* a,
                                         const uint32_t* b) {
    asm volatile("mma.sync.aligned.m16n8k16.row.col.f32.bf16.bf16.f32 "
                 "{%0,%1,%2,%3}, {%4,%5,%6,%7}, {%8,%9}, {%0,%1,%2,%3};"
                 : "+f"(c[0]), "+f"(c[1]), "+f"(c[2]), "+f"(c[3])
                 : "r"(a[0]), "r"(a[1]), "r"(a[2]), "r"(a[3]),
                   "r"(b[0]), "r"(b[1]));
}

/* ---------------- init ----------------------------------------------------- */
__global__ void init_kernel() {
    const float NEG_INF = __int_as_float(0xff800000);
    size_t t = (size_t)blockIdx.x * blockDim.x + threadIdx.x;
    if (t < (size_t)N_NODES * F1) g_out1[t] = 0.0f;
    if (t < (size_t)N_NODES * 8) g_out2[t] = 0.0f;
    if (t < (size_t)N_NODES * HEADS) { g_m1[t] = NEG_INF; g_den1[t] = 0.0f; }
    if (t < (size_t)N_NODES) { g_m2[t] = NEG_INF; g_den2[t] = 0.0f; }
}

/* ---------------- bf16 split kernels --------------------------------------- */
__global__ void split_x_kernel(const float* __restrict__ x) {
    size_t t = ((size_t)blockIdx.x * blockDim.x + threadIdx.x) * 4;
    if (t >= (size_t)N_PAD * IN_DIM) return;
    float4 v = (t < (size_t)N_NODES * IN_DIM) ? *(const float4*)(x + t)
                                              : make_float4(0.f, 0.f, 0.f, 0.f);
    float vv[4] = {v.x, v.y, v.z, v.w};
    __nv_bfloat16 hi[4], lo[4];
#pragma unroll
    for (int i = 0; i < 4; i++) {
        hi[i] = __float2bfloat16(vv[i]);
        lo[i] = __float2bfloat16(vv[i] - __bfloat162float(hi[i]));
    }
    *(uint2*)(g_xhi + t) = *(uint2*)hi;
    *(uint2*)(g_xlo + t) = *(uint2*)lo;
}
__global__ void split_w_kernel(const float* __restrict__ W1) {
    int t = blockIdx.x * blockDim.x + threadIdx.x;
    if (t >= F1 * IN_DIM) return;
    int n = t / IN_DIM, k = t - n * IN_DIM;
    float v = W1[(size_t)k * F1 + n];
    __nv_bfloat16 hi = __float2bfloat16(v);
    g_wthi[t] = hi;
    g_wtlo[t] = __float2bfloat16(v - __bfloat162float(hi));
}

/* ------- GEMM1 via mma.sync bf16x3: h1 = x @ W1 (K' = 1152) ---------------- */
/* block 128(M) x 128(N), 8 warps each 32x64, double-buffered smem            */
#define GEMM_SMEM 65536

__global__ __launch_bounds__(256, 1)
void gemm_mma_kernel() {
    extern __shared__ char smem[];
    const uint32_t sb = smem_u32(smem);
    const int tid = threadIdx.x, lane = tid & 31, wid = tid >> 5;
    const int wM = (wid & 3) * 32, wN = (wid >> 2) * 64;
    const size_t bm = (size_t)blockIdx.y * 128;
    const int bn0 = blockIdx.x * 128;

    float acc[2][8][4];
#pragma unroll
    for (int i = 0; i < 2; i++)
#pragma unroll
        for (int j = 0; j < 8; j++)
#pragma unroll
            for (int q = 0; q < 4; q++) acc[i][j][q] = 0.0f;

    uint4 stA[4], stB[4];
    const int ld_r = tid >> 1;             /* shared by A and B staging maps */

    auto gload = [&](int ch) {
        const int term = ch / 6, k0 = (ch % 6) * KC;
        const __nv_bfloat16* Ag = (term < 2) ? g_xhi : g_xlo;
        const __nv_bfloat16* Bg = (term == 1) ? g_wtlo : g_wthi;
#pragma unroll
        for (int l = 0; l < 4; l++) {
            int i = tid + l * 256;
            int r = i >> 3, c = i & 7;
            stA[l] = *(const uint4*)(Ag + (bm + r) * IN_DIM + k0 + c * 8);
            stB[l] = *(const uint4*)(Bg + (size_t)(bn0 + r) * IN_DIM + k0 + c * 8);
        }
    };
    auto sstore = [&](int buf) {
        char* base = smem + buf * 32768;
#pragma unroll
        for (int l = 0; l < 4; l++) {
            int i = tid + l * 256;
            int r = i >> 3, c = i & 7;
            uint32_t off = r * 128 + ((c ^ (r & 7)) << 4);
            *(uint4*)(base + off) = stA[l];
            *(uint4*)(base + 16384 + off) = stB[l];
        }
    };

    gload(0);
    sstore(0);
    __syncthreads();

    for (int ch = 0; ch < NCHUNK; ch++) {
        const int cur = ch & 1;
        if (ch + 1 < NCHUNK) gload(ch + 1);
        const uint32_t sbA = sb + cur * 32768;
        const uint32_t sbB = sbA + 16384;
#pragma unroll
        for (int k16 = 0; k16 < 4; k16++) {
            uint32_t a[2][4];
#pragma unroll
            for (int am = 0; am < 2; am++) {
                int r = wM + am * 16 + (lane & 15);
                int c = k16 * 2 + (lane >> 4);
                ldsm_x4(a[am], sbA + r * 128 + ((c ^ (r & 7)) << 4));
            }
#pragma unroll
            for (int bn = 0; bn < 8; bn++) {
                int n = wN + bn * 8 + (lane & 7);
                int c = k16 * 2 + ((lane >> 3) & 1);
                uint32_t b[2];
                ldsm_x2(b, sbB + n * 128 + ((c ^ (n & 7)) << 4));
                mma_bf16(acc[0][bn], a[0], b);
                mma_bf16(acc[1][bn], a[1], b);
            }
        }
        if (ch + 1 < NCHUNK) {
            sstore((ch + 1) & 1);
            __syncthreads();
        }
    }

    /* epilogue: write h1 */
    const int qr = lane >> 2, qc = (lane & 3) * 2;
#pragma unroll
    for (int am = 0; am < 2; am++) {
        size_t r0 = bm + wM + am * 16 + qr;
#pragma unroll
        for (int half = 0; half < 2; half++) {
            size_t rr = r0 + half * 8;
            if (rr < N_NODES) {
                float* dst = g_h1 + rr * F1 + bn0 + wN + qc;
#pragma unroll
                for (int bn = 0; bn < 8; bn++)
                    *(float2*)(dst + bn * 8) =
                        make_float2(acc[am][bn][half * 2], acc[am][bn][half * 2 + 1]);
            }
        }
    }
}

/* ---------------- alpha1: per-node attention logits ----------------------- */
__global__ void alpha1_kernel(const float* __restrict__ a_src,
                              const float* __restrict__ a_dst) {
    int w = (blockIdx.x * blockDim.x + threadIdx.x) >> 5;
    int lane = threadIdx.x & 31;
    if (w >= N_NODES) return;
    const float* row = g_h1 + (size_t)w * F1;
    float s[HEADS] = {0, 0, 0, 0}, d[HEADS] = {0, 0, 0, 0};
    for (int c = lane; c < F1; c += 32) {
        float v = row[c];
        int hh = c >> 7;
        s[hh] += v * a_src[c];
        d[hh] += v * a_dst[c];
    }
#pragma unroll
    for (int hh = 0; hh < HEADS; hh++) {
        float vs = s[hh], vd = d[hh];
#pragma unroll
        for (int o = 16; o; o >>= 1) {
            vs += __shfl_xor_sync(0xffffffffu, vs, o);
            vd += __shfl_xor_sync(0xffffffffu, vd, o);
        }
        if (lane == 0) { g_alS1[w * HEADS + hh] = vs; g_alD1[w * HEADS + hh] = vd; }
    }
}

/* ---------------- layer1 edge pass A: logits + segment max ---------------- */
__global__ void edge_max1(const int* __restrict__ src, const int* __restrict__ dst) {
    int t = blockIdx.x * blockDim.x + threadIdx.x;
    if (t >= N_EDGES * HEADS) return;
    int e = t >> 2, h = t & 3;
    int s = src[e], d = dst[e];
    float v = leaky(g_alS1[s * HEADS + h] + g_alD1[d * HEADS + h]);
    g_e1[t] = v;
    atomicMaxFloat(&g_m1[d * HEADS + h], v);
}

/* -------- layer1 edge pass B: exp, denom, weighted aggregate (fused) ------ */
__global__ __launch_bounds__(256)
void edge_agg1(const int* __restrict__ src, const int* __restrict__ dst) {
    int gw = (blockIdx.x * blockDim.x + threadIdx.x) >> 5;
    int lane = threadIdx.x & 31;
    if (gw >= N_EDGES * HEADS) return;
    int e = gw >> 2, h = gw & 3;
    int s = src[e], d = dst[e];
    float ex = 0.0f;
    if (lane == 0) {
        ex = __expf(g_e1[gw] - g_m1[d * HEADS + h]);
        atomicAdd(&g_den1[d * HEADS + h], ex);
    }
    ex = __shfl_sync(0xffffffffu, ex, 0);
    const float4* hv = (const float4*)g_h1;
    float4 v = hv[(size_t)s * (F1 / 4) + h * 32 + lane];
    float* o = g_out1 + (size_t)d * F1 + h * HID + lane * 4;
    red_add_v4(o, ex * v.x, ex * v.y, ex * v.z, ex * v.w);
}

/* -------- layer2: fused normalize+bias+elu, GEMV (512->5), alpha2 --------- */
__global__ void layer2_node(const float* __restrict__ W2,
                            const float* __restrict__ a_s,
                            const float* __restrict__ a_d,
                            const float* __restrict__ b1) {
    int w = (blockIdx.x * blockDim.x + threadIdx.x) >> 5;
    int lane = threadIdx.x & 31;
    if (w >= N_NODES) return;
    const float* row = g_out1 + (size_t)w * F1;
    float acc[OUT_DIM] = {0, 0, 0, 0, 0};
    for (int c = lane; c < F1; c += 32) {
        float den = g_den1[w * HEADS + (c >> 7)];
        float xv = row[c] / (den + EPS) + b1[c];
        xv = xv > 0.0f ? xv : expm1f(xv);
        const float* wr = W2 + c * OUT_DIM;
#pragma unroll
        for (int k = 0; k < OUT_DIM; k++) acc[k] += xv * wr[k];
    }
#pragma unroll
    for (int k = 0; k < OUT_DIM; k++) {
#pragma unroll
        for (int o = 16; o; o >>= 1)
            acc[k] += __shfl_xor_sync(0xffffffffu, acc[k], o);
    }
    if (lane == 0) {
        float as = 0.0f, ad = 0.0f;
#pragma unroll
        for (int k = 0; k < OUT_DIM; k++) {
            g_h2p[w * 8 + k] = acc[k];
            as += acc[k] * a_s[k];
            ad += acc[k] * a_d[k];
        }
        g_alS2[w] = as;
        g_alD2[w] = ad;
    }
}

/* -------- layer2 edge passes ---------------------------------------------- */
__global__ void edge_max2(const int* __restrict__ src, const int* __restrict__ dst) {
    int e = blockIdx.x * blockDim.x + threadIdx.x;
    if (e >= N_EDGES) return;
    int s = src[e], d = dst[e];
    float v = leaky(g_alS2[s] + g_alD2[d]);
    g_e2[e] = v;
    atomicMaxFloat(&g_m2[d], v);
}
__global__ void edge_agg2(const int* __restrict__ src, const int* __restrict__ dst) {
    int e = blockIdx.x * blockDim.x + threadIdx.x;
    if (e >= N_EDGES) return;
    int s = src[e], d = dst[e];
    float ex = __expf(g_e2[e] - g_m2[d]);
    atomicAdd(&g_den2[d], ex);
    const float4 v = *(const float4*)&g_h2p[s * 8];
    float v4 = g_h2p[s * 8 + 4];
    float* o = &g_out2[d * 8];
    red_add_v4(o, ex * v.x, ex * v.y, ex * v.z, ex * v.w);
    atomicAdd(o + 4, ex * v4);
}

/* -------- final epilogue --------------------------------------------------- */
__global__ void final_kernel(float* __restrict__ dout, const float* __restrict__ b2) {
    int t = blockIdx.x * blockDim.x + threadIdx.x;
    if (t >= N_NODES * OUT_DIM) return;
    int n = t / OUT_DIM;
    int k = t - n * OUT_DIM;
    dout[t] = g_out2[n * 8 + k] / (g_den2[n] + EPS) + b2[k];
}

/* ---------------- launch --------------------------------------------------- */
extern "C" void kernel_launch(void* const* d_in, const int* in_sizes, int n_in,
                              void* d_out, int out_size) {
    const float* x   = (const float*)d_in[0];
    const int*   ei  = (const int*)  d_in[1];
    const float* W1  = (const float*)d_in[2];
    const float* aS1 = (const float*)d_in[3];
    const float* aD1 = (const float*)d_in[4];
    const float* b1  = (const float*)d_in[5];
    const float* W2  = (const float*)d_in[6];
    const float* aS2 = (const float*)d_in[7];
    const float* aD2 = (const float*)d_in[8];
    const float* b2  = (const float*)d_in[9];
    float*       out = (float*)d_out;

    const int* src = ei;
    const int* dst = ei + N_EDGES;

    static bool attr_set = false;
    if (!attr_set) {
        cudaFuncSetAttribute(gemm_mma_kernel,
                             cudaFuncAttributeMaxDynamicSharedMemorySize, GEMM_SMEM);
        attr_set = true;
    }

    {
        size_t n = (size_t)N_NODES * F1;
        init_kernel<<<(unsigned)((n + 255) / 256), 256>>>();
    }
    split_x_kernel<<<(unsigned)(((size_t)N_PAD * IN_DIM / 4 + 255) / 256), 256>>>(x);
    split_w_kernel<<<(F1 * IN_DIM + 255) / 256, 256>>>(W1);

    gemm_mma_kernel<<<dim3(F1 / 128, N_PAD / 128), 256, GEMM_SMEM>>>();

    alpha1_kernel<<<(N_NODES * 32 + 255) / 256, 256>>>(aS1, aD1);
    edge_max1<<<(N_EDGES * HEADS + 255) / 256, 256>>>(src, dst);
    {
        long long threads = (long long)N_EDGES * HEADS * 32;
        edge_agg1<<<(unsigned)((threads + 255) / 256), 256>>>(src, dst);
    }
    layer2_node<<<(N_NODES * 32 + 255) / 256, 256>>>(W2, aS2, aD2, b1);
    edge_max2<<<(N_EDGES + 255) / 256, 256>>>(src, dst);
    edge_agg2<<<(N_EDGES + 255) / 256, 256>>>(src, dst);
    final_kernel<<<(N_NODES * OUT_DIM + 255) / 256, 256>>>(out, b2);
}

// round 5
// speedup vs baseline: 2.9080x; 1.7574x over previous
#include <cuda_runtime.h>
#include <cuda_bf16.h>
#include <math.h>
#include <stdint.h>

#define N_NODES 50000
#define N_PAD   50048            /* 391 * 128 */
#define N_EDGES 800000
#define IN_DIM  384
#define HID     128
#define HEADS   4
#define OUT_DIM 5
#define F1      (HEADS * HID)    /* 512 */
#define EPS     1e-16f
#define NEG_SLOPE 0.2f
#define KC      64               /* K per chunk */
#define NCHUNK  18               /* 3 terms * 384/64 */

/* ---------------- scratch (device globals; no allocations allowed) -------- */
__device__ float g_h1  [(size_t)N_NODES * F1];     /* 102.4MB, L2-resident */
__device__ float g_alS1[N_NODES * HEADS];
__device__ float g_alD1[N_NODES * HEADS];
__device__ float g_h2p [N_NODES * 8];              /* padded h2 [N,8] */
__device__ float g_alS2[N_NODES];
__device__ float g_alD2[N_NODES];
/* CSR by destination */
__device__ int g_cnt   [N_NODES];
__device__ int g_rowptr[N_NODES + 1];
__device__ int g_cursor[N_NODES];
__device__ int g_ssrc  [N_EDGES];
/* bf16 split operands for tensor-core GEMM1 */
__device__ __nv_bfloat16 g_xhi[(size_t)N_PAD * IN_DIM];
__device__ __nv_bfloat16 g_xlo[(size_t)N_PAD * IN_DIM];
__device__ __nv_bfloat16 g_wthi[(size_t)F1 * IN_DIM];   /* W1^T [512 x 384] */
__device__ __nv_bfloat16 g_wtlo[(size_t)F1 * IN_DIM];

/* ---------------- helpers ------------------------------------------------- */
__device__ __forceinline__ uint32_t smem_u32(const void* p) {
    uint32_t a;
    asm("{ .reg .u64 t; cvta.to.shared.u64 t, %1; cvt.u32.u64 %0, t; }"
        : "=r"(a) : "l"(p));
    return a;
}
__device__ __forceinline__ float leaky(float v) {
    return v > 0.0f ? v : NEG_SLOPE * v;
}
__device__ __forceinline__ void ldsm_x4(uint32_t* r, uint32_t addr) {
    asm volatile("ldmatrix.sync.aligned.m8n8.x4.shared.b16 {%0,%1,%2,%3}, [%4];"
                 : "=r"(r[0]), "=r"(r[1]), "=r"(r[2]), "=r"(r[3]) : "r"(addr));
}
__device__ __forceinline__ void ldsm_x2(uint32_t* r, uint32_t addr) {
    asm volatile("ldmatrix.sync.aligned.m8n8.x2.shared.b16 {%0,%1}, [%2];"
                 : "=r"(r[0]), "=r"(r[1]) : "r"(addr));
}
__device__ __forceinline__ void mma_bf16(float* c, const uint32_t* a,
                                         const uint32_t* b) {
    asm volatile("mma.sync.aligned.m16n8k16.row.col.f32.bf16.bf16.f32 "
                 "{%0,%1,%2,%3}, {%4,%5,%6,%7}, {%8,%9}, {%0,%1,%2,%3};"
                 : "+f"(c[0]), "+f"(c[1]), "+f"(c[2]), "+f"(c[3])
                 : "r"(a[0]), "r"(a[1]), "r"(a[2]), "r"(a[3]),
                   "r"(b[0]), "r"(b[1]));
}

/* ---------------- init: zero counters + h2 accumulator --------------------- */
__global__ void init_kernel() {
    int t = blockIdx.x * blockDim.x + threadIdx.x;
    if (t < N_NODES * 8) g_h2p[t] = 0.0f;
    if (t < N_NODES) g_cnt[t] = 0;
}

/* ---------------- CSR build ------------------------------------------------ */
__global__ void count_kernel(const int* __restrict__ dst) {
    int e = blockIdx.x * blockDim.x + threadIdx.x;
    if (e < N_EDGES) atomicAdd(&g_cnt[dst[e]], 1);
}
__global__ __launch_bounds__(1024)
void scan_kernel() {                 /* single block of 1024 */
    __shared__ int s[1024];
    const int PER = (N_NODES + 1023) / 1024;   /* 49 */
    const int t = threadIdx.x;
    const int base = t * PER;
    int sum = 0;
    for (int i = 0; i < PER; i++) {
        int idx = base + i;
        if (idx < N_NODES) sum += g_cnt[idx];
    }
    s[t] = sum;
    __syncthreads();
    for (int off = 1; off < 1024; off <<= 1) {
        int v = (t >= off) ? s[t - off] : 0;
        __syncthreads();
        s[t] += v;
        __syncthreads();
    }
    int run = (t > 0) ? s[t - 1] : 0;
    for (int i = 0; i < PER; i++) {
        int idx = base + i;
        if (idx < N_NODES) {
            g_rowptr[idx] = run;
            g_cursor[idx] = run;
            run += g_cnt[idx];
        }
    }
    if (t == 1023) g_rowptr[N_NODES] = s[1023];
}
__global__ void scatter_kernel(const int* __restrict__ src,
                               const int* __restrict__ dst) {
    int e = blockIdx.x * blockDim.x + threadIdx.x;
    if (e >= N_EDGES) return;
    int p = atomicAdd(&g_cursor[dst[e]], 1);
    g_ssrc[p] = src[e];
}

/* ---------------- bf16 split kernels --------------------------------------- */
__global__ void split_x_kernel(const float* __restrict__ x) {
    size_t t = ((size_t)blockIdx.x * blockDim.x + threadIdx.x) * 4;
    if (t >= (size_t)N_PAD * IN_DIM) return;
    float4 v = (t < (size_t)N_NODES * IN_DIM) ? *(const float4*)(x + t)
                                              : make_float4(0.f, 0.f, 0.f, 0.f);
    float vv[4] = {v.x, v.y, v.z, v.w};
    __nv_bfloat16 hi[4], lo[4];
#pragma unroll
    for (int i = 0; i < 4; i++) {
        hi[i] = __float2bfloat16(vv[i]);
        lo[i] = __float2bfloat16(vv[i] - __bfloat162float(hi[i]));
    }
    *(uint2*)(g_xhi + t) = *(uint2*)hi;
    *(uint2*)(g_xlo + t) = *(uint2*)lo;
}
__global__ void split_w_kernel(const float* __restrict__ W1) {
    int t = blockIdx.x * blockDim.x + threadIdx.x;
    if (t >= F1 * IN_DIM) return;
    int n = t / IN_DIM, k = t - n * IN_DIM;
    float v = W1[(size_t)k * F1 + n];
    __nv_bfloat16 hi = __float2bfloat16(v);
    g_wthi[t] = hi;
    g_wtlo[t] = __float2bfloat16(v - __bfloat162float(hi));
}

/* ------- GEMM1 via mma.sync bf16x3: h1 = x @ W1 (K' = 1152) ---------------- */
#define GEMM_SMEM 65536

__global__ __launch_bounds__(256, 1)
void gemm_mma_kernel() {
    extern __shared__ char smem[];
    const uint32_t sb = smem_u32(smem);
    const int tid = threadIdx.x, lane = tid & 31, wid = tid >> 5;
    const int wM = (wid & 3) * 32, wN = (wid >> 2) * 64;
    const size_t bm = (size_t)blockIdx.y * 128;
    const int bn0 = blockIdx.x * 128;

    float acc[2][8][4];
#pragma unroll
    for (int i = 0; i < 2; i++)
#pragma unroll
        for (int j = 0; j < 8; j++)
#pragma unroll
            for (int q = 0; q < 4; q++) acc[i][j][q] = 0.0f;

    uint4 stA[4], stB[4];

    auto gload = [&](int ch) {
        const int term = ch / 6, k0 = (ch % 6) * KC;
        const __nv_bfloat16* Ag = (term < 2) ? g_xhi : g_xlo;
        const __nv_bfloat16* Bg = (term == 1) ? g_wtlo : g_wthi;
#pragma unroll
        for (int l = 0; l < 4; l++) {
            int i = tid + l * 256;
            int r = i >> 3, c = i & 7;
            stA[l] = *(const uint4*)(Ag + (bm + r) * IN_DIM + k0 + c * 8);
            stB[l] = *(const uint4*)(Bg + (size_t)(bn0 + r) * IN_DIM + k0 + c * 8);
        }
    };
    auto sstore = [&](int buf) {
        char* base = smem + buf * 32768;
#pragma unroll
        for (int l = 0; l < 4; l++) {
            int i = tid + l * 256;
            int r = i >> 3, c = i & 7;
            uint32_t off = r * 128 + ((c ^ (r & 7)) << 4);
            *(uint4*)(base + off) = stA[l];
            *(uint4*)(base + 16384 + off) = stB[l];
        }
    };

    gload(0);
    sstore(0);
    __syncthreads();

    for (int ch = 0; ch < NCHUNK; ch++) {
        const int cur = ch & 1;
        if (ch + 1 < NCHUNK) gload(ch + 1);
        const uint32_t sbA = sb + cur * 32768;
        const uint32_t sbB = sbA + 16384;
#pragma unroll
        for (int k16 = 0; k16 < 4; k16++) {
            uint32_t a[2][4];
#pragma unroll
            for (int am = 0; am < 2; am++) {
                int r = wM + am * 16 + (lane & 15);
                int c = k16 * 2 + (lane >> 4);
                ldsm_x4(a[am], sbA + r * 128 + ((c ^ (r & 7)) << 4));
            }
#pragma unroll
            for (int bn = 0; bn < 8; bn++) {
                int n = wN + bn * 8 + (lane & 7);
                int c = k16 * 2 + ((lane >> 3) & 1);
                uint32_t b[2];
                ldsm_x2(b, sbB + n * 128 + ((c ^ (n & 7)) << 4));
                mma_bf16(acc[0][bn], a[0], b);
                mma_bf16(acc[1][bn], a[1], b);
            }
        }
        if (ch + 1 < NCHUNK) {
            sstore((ch + 1) & 1);
            __syncthreads();
        }
    }

    const int qr = lane >> 2, qc = (lane & 3) * 2;
#pragma unroll
    for (int am = 0; am < 2; am++) {
        size_t r0 = bm + wM + am * 16 + qr;
#pragma unroll
        for (int half = 0; half < 2; half++) {
            size_t rr = r0 + half * 8;
            if (rr < N_NODES) {
                float* dstp = g_h1 + rr * F1 + bn0 + wN + qc;
#pragma unroll
                for (int bn = 0; bn < 8; bn++)
                    *(float2*)(dstp + bn * 8) =
                        make_float2(acc[am][bn][half * 2], acc[am][bn][half * 2 + 1]);
            }
        }
    }
}

/* ---------------- alpha1: per-node attention logits ----------------------- */
__global__ void alpha1_kernel(const float* __restrict__ a_src,
                              const float* __restrict__ a_dst) {
    int w = (blockIdx.x * blockDim.x + threadIdx.x) >> 5;
    int lane = threadIdx.x & 31;
    if (w >= N_NODES) return;
    const float* row = g_h1 + (size_t)w * F1;
    float s[HEADS] = {0, 0, 0, 0}, d[HEADS] = {0, 0, 0, 0};
    for (int c = lane; c < F1; c += 32) {
        float v = row[c];
        int hh = c >> 7;
        s[hh] += v * a_src[c];
        d[hh] += v * a_dst[c];
    }
#pragma unroll
    for (int hh = 0; hh < HEADS; hh++) {
        float vs = s[hh], vd = d[hh];
#pragma unroll
        for (int o = 16; o; o >>= 1) {
            vs += __shfl_xor_sync(0xffffffffu, vs, o);
            vd += __shfl_xor_sync(0xffffffffu, vd, o);
        }
        if (lane == 0) { g_alS1[w * HEADS + hh] = vs; g_alD1[w * HEADS + hh] = vd; }
    }
}

/* -------- layer1 fused: softmax + aggregate + norm + bias + elu + GEMV ----- */
/* one warp per (dst, head); in-register 128-feature accumulator              */
__global__ __launch_bounds__(256)
void gat1_fused(const float* __restrict__ b1, const float* __restrict__ W2) {
    const int gw = (blockIdx.x * blockDim.x + threadIdx.x) >> 5;
    const int lane = threadIdx.x & 31;
    if (gw >= N_NODES * HEADS) return;
    const int d = gw >> 2, h = gw & 3;
    const int rs = g_rowptr[d];
    const int deg = g_rowptr[d + 1] - rs;
    const float aD = g_alD1[d * HEADS + h];

    /* pass 1: warp max over incoming-edge logits */
    float mx = -__builtin_huge_valf();
    for (int j = lane; j < deg; j += 32) {
        int s = g_ssrc[rs + j];
        mx = fmaxf(mx, leaky(g_alS1[s * HEADS + h] + aD));
    }
#pragma unroll
    for (int o = 16; o; o >>= 1)
        mx = fmaxf(mx, __shfl_xor_sync(0xffffffffu, mx, o));

    /* pass 2: exp weights + gather-accumulate in registers */
    float a0 = 0.f, a1 = 0.f, a2 = 0.f, a3 = 0.f, den = 0.f;
    for (int base = 0; base < deg; base += 32) {
        int s = 0; float ex = 0.f;
        if (base + lane < deg) {
            s = g_ssrc[rs + base + lane];
            ex = __expf(leaky(g_alS1[s * HEADS + h] + aD) - mx);
        }
        den += ex;
        const int lim = min(32, deg - base);
        for (int jj = 0; jj < lim; jj++) {
            int sj = __shfl_sync(0xffffffffu, s, jj);
            float wj = __shfl_sync(0xffffffffu, ex, jj);
            float4 v = *(const float4*)&g_h1[(size_t)sj * F1 + h * HID + lane * 4];
            a0 += wj * v.x; a1 += wj * v.y; a2 += wj * v.z; a3 += wj * v.w;
        }
    }
#pragma unroll
    for (int o = 16; o; o >>= 1)
        den += __shfl_xor_sync(0xffffffffu, den, o);
    const float inv = 1.0f / (den + EPS);

    /* normalize + bias + elu + partial GEMV into h2 */
    float p[OUT_DIM] = {0, 0, 0, 0, 0};
    float av[4] = {a0, a1, a2, a3};
#pragma unroll
    for (int q = 0; q < 4; q++) {
        const int c = h * HID + lane * 4 + q;
        float val = av[q] * inv + b1[c];
        val = val > 0.0f ? val : expm1f(val);
        const float* wr = W2 + c * OUT_DIM;
#pragma unroll
        for (int k = 0; k < OUT_DIM; k++) p[k] += val * wr[k];
    }
#pragma unroll
    for (int k = 0; k < OUT_DIM; k++) {
#pragma unroll
        for (int o = 16; o; o >>= 1)
            p[k] += __shfl_xor_sync(0xffffffffu, p[k], o);
    }
    if (lane < OUT_DIM) atomicAdd(&g_h2p[d * 8 + lane], p[lane]);
}

/* -------- alpha2 ----------------------------------------------------------- */
__global__ void alpha2_kernel(const float* __restrict__ a_s,
                              const float* __restrict__ a_d) {
    int n = blockIdx.x * blockDim.x + threadIdx.x;
    if (n >= N_NODES) return;
    float as = 0.f, ad = 0.f;
#pragma unroll
    for (int k = 0; k < OUT_DIM; k++) {
        float v = g_h2p[n * 8 + k];
        as += v * a_s[k];
        ad += v * a_d[k];
    }
    g_alS2[n] = as;
    g_alD2[n] = ad;
}

/* -------- layer2 fused: warp per dst, direct store ------------------------- */
__global__ __launch_bounds__(256)
void gat2_fused(float* __restrict__ dout, const float* __restrict__ b2) {
    const int d = (blockIdx.x * blockDim.x + threadIdx.x) >> 5;
    const int lane = threadIdx.x & 31;
    if (d >= N_NODES) return;
    const int rs = g_rowptr[d];
    const int deg = g_rowptr[d + 1] - rs;
    const float aD = g_alD2[d];

    float mx = -__builtin_huge_valf();
    for (int j = lane; j < deg; j += 32)
        mx = fmaxf(mx, leaky(g_alS2[g_ssrc[rs + j]] + aD));
#pragma unroll
    for (int o = 16; o; o >>= 1)
        mx = fmaxf(mx, __shfl_xor_sync(0xffffffffu, mx, o));

    float acc[OUT_DIM] = {0, 0, 0, 0, 0};
    float den = 0.f;
    for (int j = lane; j < deg; j += 32) {
        int s = g_ssrc[rs + j];
        float ex = __expf(leaky(g_alS2[s] + aD) - mx);
        den += ex;
#pragma unroll
        for (int k = 0; k < OUT_DIM; k++)
            acc[k] += ex * g_h2p[s * 8 + k];
    }
#pragma unroll
    for (int o = 16; o; o >>= 1) {
        den += __shfl_xor_sync(0xffffffffu, den, o);
#pragma unroll
        for (int k = 0; k < OUT_DIM; k++)
            acc[k] += __shfl_xor_sync(0xffffffffu, acc[k], o);
    }
    if (lane == 0) {
        const float inv = 1.0f / (den + EPS);
#pragma unroll
        for (int k = 0; k < OUT_DIM; k++)
            dout[d * OUT_DIM + k] = acc[k] * inv + b2[k];
    }
}

/* ---------------- launch --------------------------------------------------- */
extern "C" void kernel_launch(void* const* d_in, const int* in_sizes, int n_in,
                              void* d_out, int out_size) {
    const float* x   = (const float*)d_in[0];
    const int*   ei  = (const int*)  d_in[1];
    const float* W1  = (const float*)d_in[2];
    const float* aS1 = (const float*)d_in[3];
    const float* aD1 = (const float*)d_in[4];
    const float* b1  = (const float*)d_in[5];
    const float* W2  = (const float*)d_in[6];
    const float* aS2 = (const float*)d_in[7];
    const float* aD2 = (const float*)d_in[8];
    const float* b2  = (const float*)d_in[9];
    float*       out = (float*)d_out;

    const int* src = ei;
    const int* dst = ei + N_EDGES;

    static bool attr_set = false;
    if (!attr_set) {
        cudaFuncSetAttribute(gemm_mma_kernel,
                             cudaFuncAttributeMaxDynamicSharedMemorySize, GEMM_SMEM);
        attr_set = true;
    }

    init_kernel<<<(N_NODES * 8 + 255) / 256, 256>>>();
    split_x_kernel<<<(unsigned)(((size_t)N_PAD * IN_DIM / 4 + 255) / 256), 256>>>(x);
    split_w_kernel<<<(F1 * IN_DIM + 255) / 256, 256>>>(W1);
    count_kernel<<<(N_EDGES + 255) / 256, 256>>>(dst);
    scan_kernel<<<1, 1024>>>();
    scatter_kernel<<<(N_EDGES + 255) / 256, 256>>>(src, dst);

    gemm_mma_kernel<<<dim3(F1 / 128, N_PAD / 128), 256, GEMM_SMEM>>>();
    alpha1_kernel<<<(N_NODES * 32 + 255) / 256, 256>>>(aS1, aD1);

    gat1_fused<<<(N_NODES * HEADS * 32 + 255) / 256, 256>>>(b1, W2);
    alpha2_kernel<<<(N_NODES + 255) / 256, 256>>>(aS2, aD2);
    gat2_fused<<<(N_NODES * 32 + 255) / 256, 256>>>(out, b2);
}

// round 6
// speedup vs baseline: 3.4493x; 1.1861x over previous
#include <cuda_runtime.h>
#include <cuda_bf16.h>
#include <math.h>
#include <stdint.h>

#define N_NODES 50000
#define N_PAD   50048            /* 391 * 128 */
#define N_EDGES 800000
#define IN_DIM  384
#define HID     128
#define HEADS   4
#define OUT_DIM 5
#define F1      (HEADS * HID)    /* 512 */
#define EPS     1e-16f
#define NEG_SLOPE 0.2f
#define KC      64               /* K per chunk */
#define NCHUNK  18               /* 3 terms * 384/64 */

/* ---------------- scratch (device globals; no allocations allowed) -------- */
__device__ float g_h1  [(size_t)N_NODES * F1];     /* 102.4MB, L2-resident */
__device__ float g_alS1[N_NODES * HEADS];
__device__ float g_alD1[N_NODES * HEADS];
__device__ float g_h2p [N_NODES * 8];              /* padded h2 [N,8] */
__device__ float g_alS2[N_NODES];
__device__ float g_alD2[N_NODES];
/* CSR by destination */
__device__ int g_cnt   [N_NODES];
__device__ int g_rowptr[N_NODES + 1];
__device__ int g_cursor[N_NODES];
__device__ int g_ssrc  [N_EDGES];
/* bf16 split operands for tensor-core GEMM1 */
__device__ __nv_bfloat16 g_xhi[(size_t)N_PAD * IN_DIM];
__device__ __nv_bfloat16 g_xlo[(size_t)N_PAD * IN_DIM];
__device__ __nv_bfloat16 g_wthi[(size_t)F1 * IN_DIM];   /* W1^T [512 x 384] */
__device__ __nv_bfloat16 g_wtlo[(size_t)F1 * IN_DIM];

/* ---------------- helpers ------------------------------------------------- */
__device__ __forceinline__ uint32_t smem_u32(const void* p) {
    uint32_t a;
    asm("{ .reg .u64 t; cvta.to.shared.u64 t, %1; cvt.u32.u64 %0, t; }"
        : "=r"(a) : "l"(p));
    return a;
}
__device__ __forceinline__ float leaky(float v) {
    return v > 0.0f ? v : NEG_SLOPE * v;
}
__device__ __forceinline__ void ldsm_x4(uint32_t* r, uint32_t addr) {
    asm volatile("ldmatrix.sync.aligned.m8n8.x4.shared.b16 {%0,%1,%2,%3}, [%4];"
                 : "=r"(r[0]), "=r"(r[1]), "=r"(r[2]), "=r"(r[3]) : "r"(addr));
}
__device__ __forceinline__ void ldsm_x2(uint32_t* r, uint32_t addr) {
    asm volatile("ldmatrix.sync.aligned.m8n8.x2.shared.b16 {%0,%1}, [%2];"
                 : "=r"(r[0]), "=r"(r[1]) : "r"(addr));
}
__device__ __forceinline__ void mma_bf16(float* c, const uint32_t* a,
                                         const uint32_t* b) {
    asm volatile("mma.sync.aligned.m16n8k16.row.col.f32.bf16.bf16.f32 "
                 "{%0,%1,%2,%3}, {%4,%5,%6,%7}, {%8,%9}, {%0,%1,%2,%3};"
                 : "+f"(c[0]), "+f"(c[1]), "+f"(c[2]), "+f"(c[3])
                 : "r"(a[0]), "r"(a[1]), "r"(a[2]), "r"(a[3]),
                   "r"(b[0]), "r"(b[1]));
}
__device__ __forceinline__ void cp16(uint32_t saddr, const void* gaddr) {
    asm volatile("cp.async.cg.shared.global [%0], [%1], 16;"
                 :: "r"(saddr), "l"(gaddr));
}
#define CP_COMMIT() asm volatile("cp.async.commit_group;")
#define CP_WAIT0()  asm volatile("cp.async.wait_group 0;")

/* ---------------- init ----------------------------------------------------- */
__global__ void init_kernel() {
    int t = blockIdx.x * blockDim.x + threadIdx.x;
    if (t < N_NODES * 8) g_h2p[t] = 0.0f;
    if (t < N_NODES * HEADS) { g_alS1[t] = 0.0f; g_alD1[t] = 0.0f; }
    if (t < N_NODES) g_cnt[t] = 0;
}

/* ---------------- CSR build ------------------------------------------------ */
__global__ void count_kernel(const int* __restrict__ dst) {
    int e = blockIdx.x * blockDim.x + threadIdx.x;
    if (e < N_EDGES) atomicAdd(&g_cnt[dst[e]], 1);
}
__global__ __launch_bounds__(1024)
void scan_kernel() {                 /* single block of 1024 */
    __shared__ int s[1024];
    const int PER = (N_NODES + 1023) / 1024;   /* 49 */
    const int t = threadIdx.x;
    const int base = t * PER;
    int sum = 0;
    for (int i = 0; i < PER; i++) {
        int idx = base + i;
        if (idx < N_NODES) sum += g_cnt[idx];
    }
    s[t] = sum;
    __syncthreads();
    for (int off = 1; off < 1024; off <<= 1) {
        int v = (t >= off) ? s[t - off] : 0;
        __syncthreads();
        s[t] += v;
        __syncthreads();
    }
    int run = (t > 0) ? s[t - 1] : 0;
    for (int i = 0; i < PER; i++) {
        int idx = base + i;
        if (idx < N_NODES) {
            g_rowptr[idx] = run;
            g_cursor[idx] = run;
            run += g_cnt[idx];
        }
    }
    if (t == 1023) g_rowptr[N_NODES] = s[1023];
}
__global__ void scatter_kernel(const int* __restrict__ src,
                               const int* __restrict__ dst) {
    int e = blockIdx.x * blockDim.x + threadIdx.x;
    if (e >= N_EDGES) return;
    int p = atomicAdd(&g_cursor[dst[e]], 1);
    g_ssrc[p] = src[e];
}

/* ---------------- bf16 split kernels --------------------------------------- */
__global__ void split_x_kernel(const float* __restrict__ x) {
    size_t t = ((size_t)blockIdx.x * blockDim.x + threadIdx.x) * 4;
    if (t >= (size_t)N_PAD * IN_DIM) return;
    float4 v = (t < (size_t)N_NODES * IN_DIM) ? *(const float4*)(x + t)
                                              : make_float4(0.f, 0.f, 0.f, 0.f);
    float vv[4] = {v.x, v.y, v.z, v.w};
    __nv_bfloat16 hi[4], lo[4];
#pragma unroll
    for (int i = 0; i < 4; i++) {
        hi[i] = __float2bfloat16(vv[i]);
        lo[i] = __float2bfloat16(vv[i] - __bfloat162float(hi[i]));
    }
    *(uint2*)(g_xhi + t) = *(uint2*)hi;
    *(uint2*)(g_xlo + t) = *(uint2*)lo;
}
__global__ void split_w_kernel(const float* __restrict__ W1) {
    int t = blockIdx.x * blockDim.x + threadIdx.x;
    if (t >= F1 * IN_DIM) return;
    int n = t / IN_DIM, k = t - n * IN_DIM;
    float v = W1[(size_t)k * F1 + n];
    __nv_bfloat16 hi = __float2bfloat16(v);
    g_wthi[t] = hi;
    g_wtlo[t] = __float2bfloat16(v - __bfloat162float(hi));
}

/* ------- GEMM1 via mma.sync bf16x3, cp.async double-buffer ----------------- */
/* h1 = x @ W1 (K' = 1152); alpha1 partials fused into epilogue               */
#define GEMM_SMEM 65536

__global__ __launch_bounds__(256, 2)
void gemm_mma_kernel(const float* __restrict__ aSrc,
                     const float* __restrict__ aDst) {
    extern __shared__ char smem[];
    const uint32_t sb = smem_u32(smem);
    const int tid = threadIdx.x, lane = tid & 31, wid = tid >> 5;
    const int wM = (wid & 3) * 32, wN = (wid >> 2) * 64;
    const size_t bm = (size_t)blockIdx.y * 128;
    const int bn0 = blockIdx.x * 128;

    float acc[2][8][4];
#pragma unroll
    for (int i = 0; i < 2; i++)
#pragma unroll
        for (int j = 0; j < 8; j++)
#pragma unroll
            for (int q = 0; q < 4; q++) acc[i][j][q] = 0.0f;

    auto issue = [&](int ch, int buf) {
        const int term = ch / 6, k0 = (ch % 6) * KC;
        const __nv_bfloat16* Ag = (term < 2) ? g_xhi : g_xlo;
        const __nv_bfloat16* Bg = (term == 1) ? g_wtlo : g_wthi;
        const uint32_t base = sb + buf * 32768;
#pragma unroll
        for (int l = 0; l < 4; l++) {
            int i = tid + l * 256;
            int r = i >> 3, c = i & 7;
            uint32_t off = r * 128 + ((c ^ (r & 7)) << 4);
            cp16(base + off, Ag + (bm + r) * IN_DIM + k0 + c * 8);
            cp16(base + 16384 + off, Bg + (size_t)(bn0 + r) * IN_DIM + k0 + c * 8);
        }
        CP_COMMIT();
    };

    issue(0, 0);

    for (int ch = 0; ch < NCHUNK; ch++) {
        CP_WAIT0();
        __syncthreads();
        if (ch + 1 < NCHUNK) issue(ch + 1, (ch + 1) & 1);
        const uint32_t sbA = sb + (ch & 1) * 32768;
        const uint32_t sbB = sbA + 16384;
#pragma unroll
        for (int k16 = 0; k16 < 4; k16++) {
            uint32_t a[2][4];
#pragma unroll
            for (int am = 0; am < 2; am++) {
                int r = wM + am * 16 + (lane & 15);
                int c = k16 * 2 + (lane >> 4);
                ldsm_x4(a[am], sbA + r * 128 + ((c ^ (r & 7)) << 4));
            }
#pragma unroll
            for (int bn = 0; bn < 8; bn++) {
                int n = wN + bn * 8 + (lane & 7);
                int c = k16 * 2 + ((lane >> 3) & 1);
                uint32_t b[2];
                ldsm_x2(b, sbB + n * 128 + ((c ^ (n & 7)) << 4));
                mma_bf16(acc[0][bn], a[0], b);
                mma_bf16(acc[1][bn], a[1], b);
            }
        }
    }

    /* epilogue: write h1 + fused alpha1 partial dot products */
    const int qr = lane >> 2, qc = (lane & 3) * 2;
    const int hh = bn0 >> 7;                     /* head index of this block */
    float sA[4] = {0, 0, 0, 0}, sD[4] = {0, 0, 0, 0};   /* [am*2+half] */

#pragma unroll
    for (int am = 0; am < 2; am++) {
        size_t r0 = bm + wM + am * 16 + qr;
#pragma unroll
        for (int half = 0; half < 2; half++) {
            size_t rr = r0 + half * 8;
            if (rr < N_NODES) {
                float* dstp = g_h1 + rr * F1 + bn0 + wN + qc;
#pragma unroll
                for (int bn = 0; bn < 8; bn++) {
                    float v0 = acc[am][bn][half * 2];
                    float v1 = acc[am][bn][half * 2 + 1];
                    *(float2*)(dstp + bn * 8) = make_float2(v0, v1);
                    const int c0 = bn0 + wN + bn * 8 + qc;
                    sA[am * 2 + half] += v0 * __ldg(aSrc + c0) + v1 * __ldg(aSrc + c0 + 1);
                    sD[am * 2 + half] += v0 * __ldg(aDst + c0) + v1 * __ldg(aDst + c0 + 1);
                }
            }
        }
    }
    /* reduce across the 4 lanes sharing each row (lane & 3) */
#pragma unroll
    for (int i = 0; i < 4; i++) {
#pragma unroll
        for (int o = 1; o <= 2; o <<= 1) {
            sA[i] += __shfl_xor_sync(0xffffffffu, sA[i], o);
            sD[i] += __shfl_xor_sync(0xffffffffu, sD[i], o);
        }
    }
    if ((lane & 3) == 0) {
#pragma unroll
        for (int am = 0; am < 2; am++)
#pragma unroll
            for (int half = 0; half < 2; half++) {
                size_t rr = bm + wM + am * 16 + half * 8 + qr;
                if (rr < N_NODES) {
                    atomicAdd(&g_alS1[rr * HEADS + hh], sA[am * 2 + half]);
                    atomicAdd(&g_alD1[rr * HEADS + hh], sD[am * 2 + half]);
                }
            }
    }
}

/* -------- layer1 fused: softmax + aggregate + norm + bias + elu + GEMV ----- */
__global__ __launch_bounds__(256)
void gat1_fused(const float* __restrict__ b1, const float* __restrict__ W2) {
    const int gw = (blockIdx.x * blockDim.x + threadIdx.x) >> 5;
    const int lane = threadIdx.x & 31;
    if (gw >= N_NODES * HEADS) return;
    const int d = gw >> 2, h = gw & 3;
    const int rs = g_rowptr[d];
    const int deg = g_rowptr[d + 1] - rs;
    const float aD = g_alD1[d * HEADS + h];

    float mx = -__builtin_huge_valf();
    for (int j = lane; j < deg; j += 32) {
        int s = g_ssrc[rs + j];
        mx = fmaxf(mx, leaky(g_alS1[s * HEADS + h] + aD));
    }
#pragma unroll
    for (int o = 16; o; o >>= 1)
        mx = fmaxf(mx, __shfl_xor_sync(0xffffffffu, mx, o));

    float a0 = 0.f, a1 = 0.f, a2 = 0.f, a3 = 0.f, den = 0.f;
    for (int base = 0; base < deg; base += 32) {
        int s = 0; float ex = 0.f;
        if (base + lane < deg) {
            s = g_ssrc[rs + base + lane];
            ex = __expf(leaky(g_alS1[s * HEADS + h] + aD) - mx);
        }
        den += ex;
        const int lim = min(32, deg - base);
        for (int jj = 0; jj < lim; jj++) {
            int sj = __shfl_sync(0xffffffffu, s, jj);
            float wj = __shfl_sync(0xffffffffu, ex, jj);
            float4 v = *(const float4*)&g_h1[(size_t)sj * F1 + h * HID + lane * 4];
            a0 += wj * v.x; a1 += wj * v.y; a2 += wj * v.z; a3 += wj * v.w;
        }
    }
#pragma unroll
    for (int o = 16; o; o >>= 1)
        den += __shfl_xor_sync(0xffffffffu, den, o);
    const float inv = 1.0f / (den + EPS);

    float p[OUT_DIM] = {0, 0, 0, 0, 0};
    float av[4] = {a0, a1, a2, a3};
#pragma unroll
    for (int q = 0; q < 4; q++) {
        const int c = h * HID + lane * 4 + q;
        float val = av[q] * inv + b1[c];
        val = val > 0.0f ? val : expm1f(val);
        const float* wr = W2 + c * OUT_DIM;
#pragma unroll
        for (int k = 0; k < OUT_DIM; k++) p[k] += val * wr[k];
    }
#pragma unroll
    for (int k = 0; k < OUT_DIM; k++) {
#pragma unroll
        for (int o = 16; o; o >>= 1)
            p[k] += __shfl_xor_sync(0xffffffffu, p[k], o);
    }
    if (lane < OUT_DIM) atomicAdd(&g_h2p[d * 8 + lane], p[lane]);
}

/* -------- alpha2 ----------------------------------------------------------- */
__global__ void alpha2_kernel(const float* __restrict__ a_s,
                              const float* __restrict__ a_d) {
    int n = blockIdx.x * blockDim.x + threadIdx.x;
    if (n >= N_NODES) return;
    float as = 0.f, ad = 0.f;
#pragma unroll
    for (int k = 0; k < OUT_DIM; k++) {
        float v = g_h2p[n * 8 + k];
        as += v * a_s[k];
        ad += v * a_d[k];
    }
    g_alS2[n] = as;
    g_alD2[n] = ad;
}

/* -------- layer2 fused: warp per dst, direct store ------------------------- */
__global__ __launch_bounds__(256)
void gat2_fused(float* __restrict__ dout, const float* __restrict__ b2) {
    const int d = (blockIdx.x * blockDim.x + threadIdx.x) >> 5;
    const int lane = threadIdx.x & 31;
    if (d >= N_NODES) return;
    const int rs = g_rowptr[d];
    const int deg = g_rowptr[d + 1] - rs;
    const float aD = g_alD2[d];

    float mx = -__builtin_huge_valf();
    for (int j = lane; j < deg; j += 32)
        mx = fmaxf(mx, leaky(g_alS2[g_ssrc[rs + j]] + aD));
#pragma unroll
    for (int o = 16; o; o >>= 1)
        mx = fmaxf(mx, __shfl_xor_sync(0xffffffffu, mx, o));

    float acc[OUT_DIM] = {0, 0, 0, 0, 0};
    float den = 0.f;
    for (int j = lane; j < deg; j += 32) {
        int s = g_ssrc[rs + j];
        float ex = __expf(leaky(g_alS2[s] + aD) - mx);
        den += ex;
#pragma unroll
        for (int k = 0; k < OUT_DIM; k++)
            acc[k] += ex * g_h2p[s * 8 + k];
    }
#pragma unroll
    for (int o = 16; o; o >>= 1) {
        den += __shfl_xor_sync(0xffffffffu, den, o);
#pragma unroll
        for (int k = 0; k < OUT_DIM; k++)
            acc[k] += __shfl_xor_sync(0xffffffffu, acc[k], o);
    }
    if (lane == 0) {
        const float inv = 1.0f / (den + EPS);
#pragma unroll
        for (int k = 0; k < OUT_DIM; k++)
            dout[d * OUT_DIM + k] = acc[k] * inv + b2[k];
    }
}

/* ---------------- launch --------------------------------------------------- */
extern "C" void kernel_launch(void* const* d_in, const int* in_sizes, int n_in,
                              void* d_out, int out_size) {
    const float* x   = (const float*)d_in[0];
    const int*   ei  = (const int*)  d_in[1];
    const float* W1  = (const float*)d_in[2];
    const float* aS1 = (const float*)d_in[3];
    const float* aD1 = (const float*)d_in[4];
    const float* b1  = (const float*)d_in[5];
    const float* W2  = (const float*)d_in[6];
    const float* aS2 = (const float*)d_in[7];
    const float* aD2 = (const float*)d_in[8];
    const float* b2  = (const float*)d_in[9];
    float*       out = (float*)d_out;

    const int* src = ei;
    const int* dst = ei + N_EDGES;

    static bool attr_set = false;
    if (!attr_set) {
        cudaFuncSetAttribute(gemm_mma_kernel,
                             cudaFuncAttributeMaxDynamicSharedMemorySize, GEMM_SMEM);
        attr_set = true;
    }

    init_kernel<<<(N_NODES * 8 + 255) / 256, 256>>>();
    split_x_kernel<<<(unsigned)(((size_t)N_PAD * IN_DIM / 4 + 255) / 256), 256>>>(x);
    split_w_kernel<<<(F1 * IN_DIM + 255) / 256, 256>>>(W1);
    count_kernel<<<(N_EDGES + 255) / 256, 256>>>(dst);
    scan_kernel<<<1, 1024>>>();
    scatter_kernel<<<(N_EDGES + 255) / 256, 256>>>(src, dst);

    gemm_mma_kernel<<<dim3(F1 / 128, N_PAD / 128), 256, GEMM_SMEM>>>(aS1, aD1);

    gat1_fused<<<(N_NODES * HEADS * 32 + 255) / 256, 256>>>(b1, W2);
    alpha2_kernel<<<(N_NODES + 255) / 256, 256>>>(aS2, aD2);
    gat2_fused<<<(N_NODES * 32 + 255) / 256, 256>>>(out, b2);
}

// round 7
// speedup vs baseline: 3.4980x; 1.0141x over previous
#include <cuda_runtime.h>
#include <cuda_bf16.h>
#include <math.h>
#include <stdint.h>

#define N_NODES 50000
#define N_PAD   50048            /* 391 * 128 */
#define N_EDGES 800000
#define IN_DIM  384
#define HID     128
#define HEADS   4
#define OUT_DIM 5
#define F1      (HEADS * HID)    /* 512 */
#define EPS     1e-16f
#define NEG_SLOPE 0.2f
#define KC      64               /* K per chunk */
#define NCHUNK  18               /* 3 terms * 384/64 */
#define NEG_INF __int_as_float(0xff800000)

/* ---------------- scratch (device globals; no allocations allowed) -------- */
__device__ float g_h1  [(size_t)N_NODES * F1];     /* 102.4MB, L2-resident */
__device__ float g_alS1[N_NODES * HEADS];
__device__ float g_alD1[N_NODES * HEADS];
__device__ float g_h2p [N_NODES * 8];              /* padded h2 [N,8] */
__device__ float g_alS2[N_NODES];
__device__ float g_alD2[N_NODES];
/* CSR by destination */
__device__ int g_cnt   [N_NODES];
__device__ int g_rowptr[N_NODES + 1];
__device__ int g_cursor[N_NODES];
__device__ int g_ssrc  [N_EDGES];
/* bf16 split operands for tensor-core GEMM1 */
__device__ __nv_bfloat16 g_xhi[(size_t)N_PAD * IN_DIM];
__device__ __nv_bfloat16 g_xlo[(size_t)N_PAD * IN_DIM];
__device__ __nv_bfloat16 g_wthi[(size_t)F1 * IN_DIM];   /* W1^T [512 x 384] */
__device__ __nv_bfloat16 g_wtlo[(size_t)F1 * IN_DIM];

/* ---------------- helpers ------------------------------------------------- */
__device__ __forceinline__ uint32_t smem_u32(const void* p) {
    uint32_t a;
    asm("{ .reg .u64 t; cvta.to.shared.u64 t, %1; cvt.u32.u64 %0, t; }"
        : "=r"(a) : "l"(p));
    return a;
}
__device__ __forceinline__ float leaky(float v) {
    return v > 0.0f ? v : NEG_SLOPE * v;
}
__device__ __forceinline__ void ldsm_x4(uint32_t* r, uint32_t addr) {
    asm volatile("ldmatrix.sync.aligned.m8n8.x4.shared.b16 {%0,%1,%2,%3}, [%4];"
                 : "=r"(r[0]), "=r"(r[1]), "=r"(r[2]), "=r"(r[3]) : "r"(addr));
}
__device__ __forceinline__ void mma_bf16(float* c, const uint32_t* a,
                                         const uint32_t* b) {
    asm volatile("mma.sync.aligned.m16n8k16.row.col.f32.bf16.bf16.f32 "
                 "{%0,%1,%2,%3}, {%4,%5,%6,%7}, {%8,%9}, {%0,%1,%2,%3};"
                 : "+f"(c[0]), "+f"(c[1]), "+f"(c[2]), "+f"(c[3])
                 : "r"(a[0]), "r"(a[1]), "r"(a[2]), "r"(a[3]),
                   "r"(b[0]), "r"(b[1]));
}
__device__ __forceinline__ void cp16(uint32_t saddr, const void* gaddr) {
    asm volatile("cp.async.cg.shared.global [%0], [%1], 16;"
                 :: "r"(saddr), "l"(gaddr));
}
#define CP_COMMIT() asm volatile("cp.async.commit_group;")
#define CP_WAIT0()  asm volatile("cp.async.wait_group 0;")

/* ---------------- split_x + init (fused) ----------------------------------- */
__global__ void split_x_kernel(const float* __restrict__ x) {
    size_t tid = (size_t)blockIdx.x * blockDim.x + threadIdx.x;
    /* fused init */
    if (tid < N_NODES * 8) g_h2p[tid] = 0.0f;
    if (tid < N_NODES * HEADS) { g_alS1[tid] = 0.0f; g_alD1[tid] = 0.0f; }
    if (tid < N_NODES) g_cnt[tid] = 0;

    size_t t = tid * 4;
    if (t >= (size_t)N_PAD * IN_DIM) return;
    float4 v = (t < (size_t)N_NODES * IN_DIM) ? *(const float4*)(x + t)
                                              : make_float4(0.f, 0.f, 0.f, 0.f);
    float vv[4] = {v.x, v.y, v.z, v.w};
    __nv_bfloat16 hi[4], lo[4];
#pragma unroll
    for (int i = 0; i < 4; i++) {
        hi[i] = __float2bfloat16(vv[i]);
        lo[i] = __float2bfloat16(vv[i] - __bfloat162float(hi[i]));
    }
    *(uint2*)(g_xhi + t) = *(uint2*)hi;
    *(uint2*)(g_xlo + t) = *(uint2*)lo;
}
__global__ void split_w_kernel(const float* __restrict__ W1) {
    int t = blockIdx.x * blockDim.x + threadIdx.x;
    if (t >= F1 * IN_DIM) return;
    int n = t / IN_DIM, k = t - n * IN_DIM;
    float v = W1[(size_t)k * F1 + n];
    __nv_bfloat16 hi = __float2bfloat16(v);
    g_wthi[t] = hi;
    g_wtlo[t] = __float2bfloat16(v - __bfloat162float(hi));
}

/* ---------------- CSR build ------------------------------------------------ */
__global__ void count_kernel(const int* __restrict__ dst) {
    int e = blockIdx.x * blockDim.x + threadIdx.x;
    if (e < N_EDGES) atomicAdd(&g_cnt[dst[e]], 1);
}
__global__ __launch_bounds__(1024)
void scan_kernel() {
    __shared__ int s[1024];
    const int PER = (N_NODES + 1023) / 1024;
    const int t = threadIdx.x;
    const int base = t * PER;
    int sum = 0;
    for (int i = 0; i < PER; i++) {
        int idx = base + i;
        if (idx < N_NODES) sum += g_cnt[idx];
    }
    s[t] = sum;
    __syncthreads();
    for (int off = 1; off < 1024; off <<= 1) {
        int v = (t >= off) ? s[t - off] : 0;
        __syncthreads();
        s[t] += v;
        __syncthreads();
    }
    int run = (t > 0) ? s[t - 1] : 0;
    for (int i = 0; i < PER; i++) {
        int idx = base + i;
        if (idx < N_NODES) {
            g_rowptr[idx] = run;
            g_cursor[idx] = run;
            run += g_cnt[idx];
        }
    }
    if (t == 1023) g_rowptr[N_NODES] = s[1023];
}
__global__ void scatter_kernel(const int* __restrict__ src,
                               const int* __restrict__ dst) {
    int e = blockIdx.x * blockDim.x + threadIdx.x;
    if (e >= N_EDGES) return;
    int p = atomicAdd(&g_cursor[dst[e]], 1);
    g_ssrc[p] = src[e];
}

/* ------- GEMM1 via mma.sync bf16x3, cp.async double-buffer ----------------- */
#define GEMM_SMEM 65536

__global__ __launch_bounds__(256, 2)
void gemm_mma_kernel(const float* __restrict__ aSrc,
                     const float* __restrict__ aDst) {
    extern __shared__ char smem[];
    const uint32_t sb = smem_u32(smem);
    const int tid = threadIdx.x, lane = tid & 31, wid = tid >> 5;
    const int wM = (wid & 3) * 32, wN = (wid >> 2) * 64;
    const size_t bm = (size_t)blockIdx.y * 128;
    const int bn0 = blockIdx.x * 128;

    float acc[2][8][4];
#pragma unroll
    for (int i = 0; i < 2; i++)
#pragma unroll
        for (int j = 0; j < 8; j++)
#pragma unroll
            for (int q = 0; q < 4; q++) acc[i][j][q] = 0.0f;

    auto issue = [&](int ch, int buf) {
        const int term = ch / 6, k0 = (ch % 6) * KC;
        const __nv_bfloat16* Ag = (term < 2) ? g_xhi : g_xlo;
        const __nv_bfloat16* Bg = (term == 1) ? g_wtlo : g_wthi;
        const uint32_t base = sb + buf * 32768;
#pragma unroll
        for (int l = 0; l < 4; l++) {
            int i = tid + l * 256;
            int r = i >> 3, c = i & 7;
            uint32_t off = r * 128 + ((c ^ (r & 7)) << 4);
            cp16(base + off, Ag + (bm + r) * IN_DIM + k0 + c * 8);
            cp16(base + 16384 + off, Bg + (size_t)(bn0 + r) * IN_DIM + k0 + c * 8);
        }
        CP_COMMIT();
    };

    issue(0, 0);

    for (int ch = 0; ch < NCHUNK; ch++) {
        CP_WAIT0();
        __syncthreads();
        if (ch + 1 < NCHUNK) issue(ch + 1, (ch + 1) & 1);
        const uint32_t sbA = sb + (ch & 1) * 32768;
        const uint32_t sbB = sbA + 16384;
#pragma unroll
        for (int k16 = 0; k16 < 4; k16++) {
            uint32_t a[2][4];
#pragma unroll
            for (int am = 0; am < 2; am++) {
                int r = wM + am * 16 + (lane & 15);
                int c = k16 * 2 + (lane >> 4);
                ldsm_x4(a[am], sbA + r * 128 + ((c ^ (r & 7)) << 4));
            }
#pragma unroll
            for (int bn2 = 0; bn2 < 4; bn2++) {
                /* x4 serves two n8 tiles: lanes 0-15 -> bn2*2, 16-31 -> bn2*2+1 */
                int n = wN + bn2 * 16 + ((lane >> 4) << 3) + (lane & 7);
                int c = k16 * 2 + ((lane >> 3) & 1);
                uint32_t b[4];
                ldsm_x4(b, sbB + n * 128 + ((c ^ (n & 7)) << 4));
                mma_bf16(acc[0][bn2 * 2], a[0], b);
                mma_bf16(acc[1][bn2 * 2], a[1], b);
                mma_bf16(acc[0][bn2 * 2 + 1], a[0], b + 2);
                mma_bf16(acc[1][bn2 * 2 + 1], a[1], b + 2);
            }
        }
    }

    /* epilogue: write h1 + fused alpha1 partial dot products */
    const int qr = lane >> 2, qc = (lane & 3) * 2;
    const int hh = bn0 >> 7;
    float sA[4] = {0, 0, 0, 0}, sD[4] = {0, 0, 0, 0};

#pragma unroll
    for (int am = 0; am < 2; am++) {
        size_t r0 = bm + wM + am * 16 + qr;
#pragma unroll
        for (int half = 0; half < 2; half++) {
            size_t rr = r0 + half * 8;
            if (rr < N_NODES) {
                float* dstp = g_h1 + rr * F1 + bn0 + wN + qc;
#pragma unroll
                for (int bn = 0; bn < 8; bn++) {
                    float v0 = acc[am][bn][half * 2];
                    float v1 = acc[am][bn][half * 2 + 1];
                    *(float2*)(dstp + bn * 8) = make_float2(v0, v1);
                    const int c0 = bn0 + wN + bn * 8 + qc;
                    sA[am * 2 + half] += v0 * __ldg(aSrc + c0) + v1 * __ldg(aSrc + c0 + 1);
                    sD[am * 2 + half] += v0 * __ldg(aDst + c0) + v1 * __ldg(aDst + c0 + 1);
                }
            }
        }
    }
#pragma unroll
    for (int i = 0; i < 4; i++) {
#pragma unroll
        for (int o = 1; o <= 2; o <<= 1) {
            sA[i] += __shfl_xor_sync(0xffffffffu, sA[i], o);
            sD[i] += __shfl_xor_sync(0xffffffffu, sD[i], o);
        }
    }
    if ((lane & 3) == 0) {
#pragma unroll
        for (int am = 0; am < 2; am++)
#pragma unroll
            for (int half = 0; half < 2; half++) {
                size_t rr = bm + wM + am * 16 + half * 8 + qr;
                if (rr < N_NODES) {
                    atomicAdd(&g_alS1[rr * HEADS + hh], sA[am * 2 + half]);
                    atomicAdd(&g_alD1[rr * HEADS + hh], sD[am * 2 + half]);
                }
            }
    }
}

/* -------- layer1 fused: online softmax + aggregate + elu + GEMV ------------ */
__global__ __launch_bounds__(256)
void gat1_fused(const float* __restrict__ b1, const float* __restrict__ W2) {
    const int gw = (blockIdx.x * blockDim.x + threadIdx.x) >> 5;
    const int lane = threadIdx.x & 31;
    if (gw >= N_NODES * HEADS) return;
    const int d = gw >> 2, h = gw & 3;
    const int rs = g_rowptr[d];
    const int deg = g_rowptr[d + 1] - rs;
    const float aD = g_alD1[d * HEADS + h];
    const float* __restrict__ hbase = g_h1 + h * HID + lane * 4;

    float m = NEG_INF;
    float den = 0.f, a0 = 0.f, a1 = 0.f, a2 = 0.f, a3 = 0.f;

    for (int base = 0; base < deg; base += 32) {
        int s = 0;
        float lg = NEG_INF;
        if (base + lane < deg) {
            s = g_ssrc[rs + base + lane];
            lg = leaky(g_alS1[s * HEADS + h] + aD);
        }
        float bmx = lg;
#pragma unroll
        for (int o = 16; o; o >>= 1)
            bmx = fmaxf(bmx, __shfl_xor_sync(0xffffffffu, bmx, o));
        const float mnew = fmaxf(m, bmx);
        const float scale = __expf(m - mnew);   /* first batch: exp(-inf)=0 */
        den *= scale; a0 *= scale; a1 *= scale; a2 *= scale; a3 *= scale;
        float ex = 0.f;
        if (base + lane < deg) ex = __expf(lg - mnew);
        den += ex;
        m = mnew;

        const int lim = min(32, deg - base);
        for (int jj = 0; jj < lim; jj += 4) {
            /* clamped indices: lanes >= lim carry ex=0, s=0 -> harmless */
            const int i1 = min(jj + 1, 31), i2 = min(jj + 2, 31), i3 = min(jj + 3, 31);
            int s0 = __shfl_sync(0xffffffffu, s, jj);
            int s1 = __shfl_sync(0xffffffffu, s, i1);
            int s2 = __shfl_sync(0xffffffffu, s, i2);
            int s3 = __shfl_sync(0xffffffffu, s, i3);
            float w0 = __shfl_sync(0xffffffffu, ex, jj);
            float w1 = __shfl_sync(0xffffffffu, ex, i1);
            float w2 = __shfl_sync(0xffffffffu, ex, i2);
            float w3 = __shfl_sync(0xffffffffu, ex, i3);
            if (jj + 1 >= lim) w1 = 0.f;
            if (jj + 2 >= lim) w2 = 0.f;
            if (jj + 3 >= lim) w3 = 0.f;
            const float4 v0 = *(const float4*)(hbase + (size_t)s0 * F1);
            const float4 v1 = *(const float4*)(hbase + (size_t)s1 * F1);
            const float4 v2 = *(const float4*)(hbase + (size_t)s2 * F1);
            const float4 v3 = *(const float4*)(hbase + (size_t)s3 * F1);
            a0 += w0 * v0.x + w1 * v1.x + w2 * v2.x + w3 * v3.x;
            a1 += w0 * v0.y + w1 * v1.y + w2 * v2.y + w3 * v3.y;
            a2 += w0 * v0.z + w1 * v1.z + w2 * v2.z + w3 * v3.z;
            a3 += w0 * v0.w + w1 * v1.w + w2 * v2.w + w3 * v3.w;
        }
    }
#pragma unroll
    for (int o = 16; o; o >>= 1)
        den += __shfl_xor_sync(0xffffffffu, den, o);
    const float inv = 1.0f / (den + EPS);

    float p[OUT_DIM] = {0, 0, 0, 0, 0};
    float av[4] = {a0, a1, a2, a3};
#pragma unroll
    for (int q = 0; q < 4; q++) {
        const int c = h * HID + lane * 4 + q;
        float val = av[q] * inv + b1[c];
        val = val > 0.0f ? val : expm1f(val);
        const float* wr = W2 + c * OUT_DIM;
#pragma unroll
        for (int k = 0; k < OUT_DIM; k++) p[k] += val * wr[k];
    }
#pragma unroll
    for (int k = 0; k < OUT_DIM; k++) {
#pragma unroll
        for (int o = 16; o; o >>= 1)
            p[k] += __shfl_xor_sync(0xffffffffu, p[k], o);
    }
    if (lane < OUT_DIM) atomicAdd(&g_h2p[d * 8 + lane], p[lane]);
}

/* -------- alpha2 ----------------------------------------------------------- */
__global__ void alpha2_kernel(const float* __restrict__ a_s,
                              const float* __restrict__ a_d) {
    int n = blockIdx.x * blockDim.x + threadIdx.x;
    if (n >= N_NODES) return;
    float as = 0.f, ad = 0.f;
#pragma unroll
    for (int k = 0; k < OUT_DIM; k++) {
        float v = g_h2p[n * 8 + k];
        as += v * a_s[k];
        ad += v * a_d[k];
    }
    g_alS2[n] = as;
    g_alD2[n] = ad;
}

/* -------- layer2 fused: per-lane online softmax, direct store -------------- */
__global__ __launch_bounds__(256)
void gat2_fused(float* __restrict__ dout, const float* __restrict__ b2) {
    const int d = (blockIdx.x * blockDim.x + threadIdx.x) >> 5;
    const int lane = threadIdx.x & 31;
    if (d >= N_NODES) return;
    const int rs = g_rowptr[d];
    const int deg = g_rowptr[d + 1] - rs;
    if (deg == 0) {
        if (lane == 0) {
#pragma unroll
            for (int k = 0; k < OUT_DIM; k++)
                dout[d * OUT_DIM + k] = b2[k];
        }
        return;
    }
    const float aD = g_alD2[d];

    float m = NEG_INF, den = 0.f;
    float acc[OUT_DIM] = {0, 0, 0, 0, 0};
    for (int j = lane; j < deg; j += 32) {
        int s = g_ssrc[rs + j];
        float lg = leaky(g_alS2[s] + aD);
        float mnew = fmaxf(m, lg);
        float sc = __expf(m - mnew);
        float ex = __expf(lg - mnew);
        den = den * sc + ex;
#pragma unroll
        for (int k = 0; k < OUT_DIM; k++)
            acc[k] = acc[k] * sc + ex * g_h2p[s * 8 + k];
        m = mnew;
    }
    /* merge lanes */
    float M = m;
#pragma unroll
    for (int o = 16; o; o >>= 1)
        M = fmaxf(M, __shfl_xor_sync(0xffffffffu, M, o));
    float sc = __expf(m - M);     /* edgeless lane: exp(-inf - finite) = 0 */
    den *= sc;
#pragma unroll
    for (int k = 0; k < OUT_DIM; k++) acc[k] *= sc;
#pragma unroll
    for (int o = 16; o; o >>= 1) {
        den += __shfl_xor_sync(0xffffffffu, den, o);
#pragma unroll
        for (int k = 0; k < OUT_DIM; k++)
            acc[k] += __shfl_xor_sync(0xffffffffu, acc[k], o);
    }
    if (lane == 0) {
        const float inv = 1.0f / (den + EPS);
#pragma unroll
        for (int k = 0; k < OUT_DIM; k++)
            dout[d * OUT_DIM + k] = acc[k] * inv + b2[k];
    }
}

/* ---------------- launch --------------------------------------------------- */
extern "C" void kernel_launch(void* const* d_in, const int* in_sizes, int n_in,
                              void* d_out, int out_size) {
    const float* x   = (const float*)d_in[0];
    const int*   ei  = (const int*)  d_in[1];
    const float* W1  = (const float*)d_in[2];
    const float* aS1 = (const float*)d_in[3];
    const float* aD1 = (const float*)d_in[4];
    const float* b1  = (const float*)d_in[5];
    const float* W2  = (const float*)d_in[6];
    const float* aS2 = (const float*)d_in[7];
    const float* aD2 = (const float*)d_in[8];
    const float* b2  = (const float*)d_in[9];
    float*       out = (float*)d_out;

    const int* src = ei;
    const int* dst = ei + N_EDGES;

    static bool attr_set = false;
    if (!attr_set) {
        cudaFuncSetAttribute(gemm_mma_kernel,
                             cudaFuncAttributeMaxDynamicSharedMemorySize, GEMM_SMEM);
        attr_set = true;
    }

    split_x_kernel<<<(unsigned)(((size_t)N_PAD * IN_DIM / 4 + 255) / 256), 256>>>(x);
    split_w_kernel<<<(F1 * IN_DIM + 255) / 256, 256>>>(W1);
    count_kernel<<<(N_EDGES + 255) / 256, 256>>>(dst);
    scan_kernel<<<1, 1024>>>();
    scatter_kernel<<<(N_EDGES + 255) / 256, 256>>>(src, dst);

    gemm_mma_kernel<<<dim3(F1 / 128, N_PAD / 128), 256, GEMM_SMEM>>>(aS1, aD1);

    gat1_fused<<<(N_NODES * HEADS * 32 + 255) / 256, 256>>>(b1, W2);
    alpha2_kernel<<<(N_NODES + 255) / 256, 256>>>(aS2, aD2);
    gat2_fused<<<(N_NODES * 32 + 255) / 256, 256>>>(out, b2);
}

// round 8
// speedup vs baseline: 3.9054x; 1.1165x over previous
#include <cuda_runtime.h>
#include <cuda_bf16.h>
#include <math.h>
#include <stdint.h>

#define N_NODES 50000
#define N_PAD   50048            /* 391 * 128 */
#define N_EDGES 800000
#define IN_DIM  384
#define HID     128
#define HEADS   4
#define OUT_DIM 5
#define F1      (HEADS * HID)    /* 512 */
#define EPS     1e-16f
#define NEG_SLOPE 0.2f
#define KC      64               /* K per chunk */
#define NCHUNK  18               /* 3 terms * 384/64 */
#define NEG_INF __int_as_float(0xff800000)
#define SCAN_NBLK ((N_NODES + 1023) / 1024)   /* 49 */

/* ---------------- scratch (device globals; no allocations allowed) -------- */
__device__ float g_h1  [(size_t)N_NODES * F1];     /* 102.4MB, L2-resident */
__device__ float g_alS1[N_NODES * HEADS];
__device__ float g_alD1[N_NODES * HEADS];
__device__ float g_h2p [N_NODES * 8];              /* padded h2 [N,8] */
__device__ float g_alS2[N_NODES];
__device__ float g_alD2[N_NODES];
/* CSR by destination */
__device__ int g_cnt   [N_NODES];
__device__ int g_rowptr[N_NODES + 1];
__device__ int g_cursor[N_NODES];
__device__ int g_ssrc  [N_EDGES];
__device__ int g_bsum  [SCAN_NBLK];
/* bf16 split operands for tensor-core GEMM1 */
__device__ __nv_bfloat16 g_xhi[(size_t)N_PAD * IN_DIM];
__device__ __nv_bfloat16 g_xlo[(size_t)N_PAD * IN_DIM];
__device__ __nv_bfloat16 g_wthi[(size_t)F1 * IN_DIM];   /* W1^T [512 x 384] */
__device__ __nv_bfloat16 g_wtlo[(size_t)F1 * IN_DIM];

/* ---------------- helpers ------------------------------------------------- */
__device__ __forceinline__ uint32_t smem_u32(const void* p) {
    uint32_t a;
    asm("{ .reg .u64 t; cvta.to.shared.u64 t, %1; cvt.u32.u64 %0, t; }"
        : "=r"(a) : "l"(p));
    return a;
}
__device__ __forceinline__ float leaky(float v) {
    return v > 0.0f ? v : NEG_SLOPE * v;
}
__device__ __forceinline__ void ldsm_x4(uint32_t* r, uint32_t addr) {
    asm volatile("ldmatrix.sync.aligned.m8n8.x4.shared.b16 {%0,%1,%2,%3}, [%4];"
                 : "=r"(r[0]), "=r"(r[1]), "=r"(r[2]), "=r"(r[3]) : "r"(addr));
}
__device__ __forceinline__ void mma_bf16(float* c, const uint32_t* a,
                                         const uint32_t* b) {
    asm volatile("mma.sync.aligned.m16n8k16.row.col.f32.bf16.bf16.f32 "
                 "{%0,%1,%2,%3}, {%4,%5,%6,%7}, {%8,%9}, {%0,%1,%2,%3};"
                 : "+f"(c[0]), "+f"(c[1]), "+f"(c[2]), "+f"(c[3])
                 : "r"(a[0]), "r"(a[1]), "r"(a[2]), "r"(a[3]),
                   "r"(b[0]), "r"(b[1]));
}
__device__ __forceinline__ void cp16(uint32_t saddr, const void* gaddr) {
    asm volatile("cp.async.cg.shared.global [%0], [%1], 16;"
                 :: "r"(saddr), "l"(gaddr));
}
#define CP_COMMIT() asm volatile("cp.async.commit_group;")
#define CP_WAIT0()  asm volatile("cp.async.wait_group 0;")

/* ---------------- split_x + init (fused) ----------------------------------- */
__global__ void split_x_kernel(const float* __restrict__ x) {
    size_t tid = (size_t)blockIdx.x * blockDim.x + threadIdx.x;
    /* fused init */
    if (tid < N_NODES * 8) g_h2p[tid] = 0.0f;
    if (tid < N_NODES * HEADS) { g_alS1[tid] = 0.0f; g_alD1[tid] = 0.0f; }
    if (tid < N_NODES) g_cnt[tid] = 0;

    size_t t = tid * 4;
    if (t >= (size_t)N_PAD * IN_DIM) return;
    float4 v = (t < (size_t)N_NODES * IN_DIM) ? *(const float4*)(x + t)
                                              : make_float4(0.f, 0.f, 0.f, 0.f);
    float vv[4] = {v.x, v.y, v.z, v.w};
    __nv_bfloat16 hi[4], lo[4];
#pragma unroll
    for (int i = 0; i < 4; i++) {
        hi[i] = __float2bfloat16(vv[i]);
        lo[i] = __float2bfloat16(vv[i] - __bfloat162float(hi[i]));
    }
    *(uint2*)(g_xhi + t) = *(uint2*)hi;
    *(uint2*)(g_xlo + t) = *(uint2*)lo;
}
__global__ void split_w_kernel(const float* __restrict__ W1) {
    int t = blockIdx.x * blockDim.x + threadIdx.x;
    if (t >= F1 * IN_DIM) return;
    int n = t / IN_DIM, k = t - n * IN_DIM;
    float v = W1[(size_t)k * F1 + n];
    __nv_bfloat16 hi = __float2bfloat16(v);
    g_wthi[t] = hi;
    g_wtlo[t] = __float2bfloat16(v - __bfloat162float(hi));
}

/* ---------------- CSR build (3-kernel parallel scan) ----------------------- */
__global__ void count_kernel(const int* __restrict__ dst) {
    int e = blockIdx.x * blockDim.x + threadIdx.x;
    if (e < N_EDGES) atomicAdd(&g_cnt[dst[e]], 1);
}
__global__ __launch_bounds__(1024)
void scan1_kernel() {                 /* per-block Hillis-Steele */
    __shared__ int s[1024];
    const int t = threadIdx.x;
    const int g = blockIdx.x * 1024 + t;
    const int v = (g < N_NODES) ? g_cnt[g] : 0;
    s[t] = v;
    __syncthreads();
#pragma unroll
    for (int off = 1; off < 1024; off <<= 1) {
        int x = (t >= off) ? s[t - off] : 0;
        __syncthreads();
        s[t] += x;
        __syncthreads();
    }
    if (g < N_NODES) g_rowptr[g] = s[t] - v;     /* exclusive partial */
    if (t == 1023) g_bsum[blockIdx.x] = s[1023];
}
__global__ void scan2_kernel() {      /* tiny serial scan of 49 block sums */
    if (threadIdx.x == 0) {
        int run = 0;
#pragma unroll 1
        for (int i = 0; i < SCAN_NBLK; i++) {
            int v = g_bsum[i];
            g_bsum[i] = run;
            run += v;
        }
        g_rowptr[N_NODES] = run;
    }
}
__global__ void scan3_kernel() {      /* add block offsets, fill cursor */
    int g = blockIdx.x * blockDim.x + threadIdx.x;
    if (g < N_NODES) {
        int v = g_rowptr[g] + g_bsum[g >> 10];
        g_rowptr[g] = v;
        g_cursor[g] = v;
    }
}
__global__ void scatter_kernel(const int* __restrict__ src,
                               const int* __restrict__ dst) {
    int e = blockIdx.x * blockDim.x + threadIdx.x;
    if (e >= N_EDGES) return;
    int p = atomicAdd(&g_cursor[dst[e]], 1);
    g_ssrc[p] = src[e];
}

/* ------- GEMM1 via mma.sync bf16x3, cp.async double-buffer ----------------- */
#define GEMM_SMEM 65536

__global__ __launch_bounds__(256, 2)
void gemm_mma_kernel(const float* __restrict__ aSrc,
                     const float* __restrict__ aDst) {
    extern __shared__ char smem[];
    const uint32_t sb = smem_u32(smem);
    const int tid = threadIdx.x, lane = tid & 31, wid = tid >> 5;
    const int wM = (wid & 3) * 32, wN = (wid >> 2) * 64;
    const size_t bm = (size_t)blockIdx.y * 128;
    const int bn0 = blockIdx.x * 128;

    float acc[2][8][4];
#pragma unroll
    for (int i = 0; i < 2; i++)
#pragma unroll
        for (int j = 0; j < 8; j++)
#pragma unroll
            for (int q = 0; q < 4; q++) acc[i][j][q] = 0.0f;

    auto issue = [&](int ch, int buf) {
        const int term = ch / 6, k0 = (ch % 6) * KC;
        const __nv_bfloat16* Ag = (term < 2) ? g_xhi : g_xlo;
        const __nv_bfloat16* Bg = (term == 1) ? g_wtlo : g_wthi;
        const uint32_t base = sb + buf * 32768;
#pragma unroll
        for (int l = 0; l < 4; l++) {
            int i = tid + l * 256;
            int r = i >> 3, c = i & 7;
            uint32_t off = r * 128 + ((c ^ (r & 7)) << 4);
            cp16(base + off, Ag + (bm + r) * IN_DIM + k0 + c * 8);
            cp16(base + 16384 + off, Bg + (size_t)(bn0 + r) * IN_DIM + k0 + c * 8);
        }
        CP_COMMIT();
    };

    issue(0, 0);

    for (int ch = 0; ch < NCHUNK; ch++) {
        CP_WAIT0();
        __syncthreads();
        if (ch + 1 < NCHUNK) issue(ch + 1, (ch + 1) & 1);
        const uint32_t sbA = sb + (ch & 1) * 32768;
        const uint32_t sbB = sbA + 16384;
#pragma unroll
        for (int k16 = 0; k16 < 4; k16++) {
            uint32_t a[2][4];
#pragma unroll
            for (int am = 0; am < 2; am++) {
                int r = wM + am * 16 + (lane & 15);
                int c = k16 * 2 + (lane >> 4);
                ldsm_x4(a[am], sbA + r * 128 + ((c ^ (r & 7)) << 4));
            }
#pragma unroll
            for (int bn2 = 0; bn2 < 4; bn2++) {
                int n = wN + bn2 * 16 + ((lane >> 4) << 3) + (lane & 7);
                int c = k16 * 2 + ((lane >> 3) & 1);
                uint32_t b[4];
                ldsm_x4(b, sbB + n * 128 + ((c ^ (n & 7)) << 4));
                mma_bf16(acc[0][bn2 * 2], a[0], b);
                mma_bf16(acc[1][bn2 * 2], a[1], b);
                mma_bf16(acc[0][bn2 * 2 + 1], a[0], b + 2);
                mma_bf16(acc[1][bn2 * 2 + 1], a[1], b + 2);
            }
        }
    }

    /* epilogue: write h1 + fused alpha1 partial dot products */
    const int qr = lane >> 2, qc = (lane & 3) * 2;
    const int hh = bn0 >> 7;
    float sA[4] = {0, 0, 0, 0}, sD[4] = {0, 0, 0, 0};

#pragma unroll
    for (int am = 0; am < 2; am++) {
        size_t r0 = bm + wM + am * 16 + qr;
#pragma unroll
        for (int half = 0; half < 2; half++) {
            size_t rr = r0 + half * 8;
            if (rr < N_NODES) {
                float* dstp = g_h1 + rr * F1 + bn0 + wN + qc;
#pragma unroll
                for (int bn = 0; bn < 8; bn++) {
                    float v0 = acc[am][bn][half * 2];
                    float v1 = acc[am][bn][half * 2 + 1];
                    *(float2*)(dstp + bn * 8) = make_float2(v0, v1);
                    const int c0 = bn0 + wN + bn * 8 + qc;
                    sA[am * 2 + half] += v0 * __ldg(aSrc + c0) + v1 * __ldg(aSrc + c0 + 1);
                    sD[am * 2 + half] += v0 * __ldg(aDst + c0) + v1 * __ldg(aDst + c0 + 1);
                }
            }
        }
    }
#pragma unroll
    for (int i = 0; i < 4; i++) {
#pragma unroll
        for (int o = 1; o <= 2; o <<= 1) {
            sA[i] += __shfl_xor_sync(0xffffffffu, sA[i], o);
            sD[i] += __shfl_xor_sync(0xffffffffu, sD[i], o);
        }
    }
    if ((lane & 3) == 0) {
#pragma unroll
        for (int am = 0; am < 2; am++)
#pragma unroll
            for (int half = 0; half < 2; half++) {
                size_t rr = bm + wM + am * 16 + half * 8 + qr;
                if (rr < N_NODES) {
                    atomicAdd(&g_alS1[rr * HEADS + hh], sA[am * 2 + half]);
                    atomicAdd(&g_alD1[rr * HEADS + hh], sD[am * 2 + half]);
                }
            }
    }
}

/* -------- layer1 fused: online softmax + aggregate + elu + GEMV ------------ */
__global__ __launch_bounds__(256)
void gat1_fused(const float* __restrict__ b1, const float* __restrict__ W2) {
    const int gw = (blockIdx.x * blockDim.x + threadIdx.x) >> 5;
    const int lane = threadIdx.x & 31;
    if (gw >= N_NODES * HEADS) return;
    const int d = gw >> 2, h = gw & 3;
    const int rs = g_rowptr[d];
    const int deg = g_rowptr[d + 1] - rs;
    const float aD = g_alD1[d * HEADS + h];
    const float* __restrict__ hbase = g_h1 + h * HID + lane * 4;

    float m = NEG_INF;
    float den = 0.f, a0 = 0.f, a1 = 0.f, a2 = 0.f, a3 = 0.f;

    for (int base = 0; base < deg; base += 32) {
        int s = 0;
        float lg = NEG_INF;
        if (base + lane < deg) {
            s = g_ssrc[rs + base + lane];
            lg = leaky(g_alS1[s * HEADS + h] + aD);
        }
        float bmx = lg;
#pragma unroll
        for (int o = 16; o; o >>= 1)
            bmx = fmaxf(bmx, __shfl_xor_sync(0xffffffffu, bmx, o));
        const float mnew = fmaxf(m, bmx);
        const float scale = __expf(m - mnew);
        den *= scale; a0 *= scale; a1 *= scale; a2 *= scale; a3 *= scale;
        float ex = 0.f;
        if (base + lane < deg) ex = __expf(lg - mnew);
        den += ex;
        m = mnew;

        const int lim = min(32, deg - base);
        for (int jj = 0; jj < lim; jj += 4) {
            const int i1 = min(jj + 1, 31), i2 = min(jj + 2, 31), i3 = min(jj + 3, 31);
            int s0 = __shfl_sync(0xffffffffu, s, jj);
            int s1 = __shfl_sync(0xffffffffu, s, i1);
            int s2 = __shfl_sync(0xffffffffu, s, i2);
            int s3 = __shfl_sync(0xffffffffu, s, i3);
            float w0 = __shfl_sync(0xffffffffu, ex, jj);
            float w1 = __shfl_sync(0xffffffffu, ex, i1);
            float w2 = __shfl_sync(0xffffffffu, ex, i2);
            float w3 = __shfl_sync(0xffffffffu, ex, i3);
            if (jj + 1 >= lim) w1 = 0.f;
            if (jj + 2 >= lim) w2 = 0.f;
            if (jj + 3 >= lim) w3 = 0.f;
            const float4 v0 = *(const float4*)(hbase + (size_t)s0 * F1);
            const float4 v1 = *(const float4*)(hbase + (size_t)s1 * F1);
            const float4 v2 = *(const float4*)(hbase + (size_t)s2 * F1);
            const float4 v3 = *(const float4*)(hbase + (size_t)s3 * F1);
            a0 += w0 * v0.x + w1 * v1.x + w2 * v2.x + w3 * v3.x;
            a1 += w0 * v0.y + w1 * v1.y + w2 * v2.y + w3 * v3.y;
            a2 += w0 * v0.z + w1 * v1.z + w2 * v2.z + w3 * v3.z;
            a3 += w0 * v0.w + w1 * v1.w + w2 * v2.w + w3 * v3.w;
        }
    }
#pragma unroll
    for (int o = 16; o; o >>= 1)
        den += __shfl_xor_sync(0xffffffffu, den, o);
    const float inv = 1.0f / (den + EPS);

    float p[OUT_DIM] = {0, 0, 0, 0, 0};
    float av[4] = {a0, a1, a2, a3};
#pragma unroll
    for (int q = 0; q < 4; q++) {
        const int c = h * HID + lane * 4 + q;
        float val = av[q] * inv + b1[c];
        val = val > 0.0f ? val : expm1f(val);
        const float* wr = W2 + c * OUT_DIM;
#pragma unroll
        for (int k = 0; k < OUT_DIM; k++) p[k] += val * wr[k];
    }
#pragma unroll
    for (int k = 0; k < OUT_DIM; k++) {
#pragma unroll
        for (int o = 16; o; o >>= 1)
            p[k] += __shfl_xor_sync(0xffffffffu, p[k], o);
    }
    if (lane < OUT_DIM) atomicAdd(&g_h2p[d * 8 + lane], p[lane]);
}

/* -------- alpha2 ----------------------------------------------------------- */
__global__ void alpha2_kernel(const float* __restrict__ a_s,
                              const float* __restrict__ a_d) {
    int n = blockIdx.x * blockDim.x + threadIdx.x;
    if (n >= N_NODES) return;
    float as = 0.f, ad = 0.f;
#pragma unroll
    for (int k = 0; k < OUT_DIM; k++) {
        float v = g_h2p[n * 8 + k];
        as += v * a_s[k];
        ad += v * a_d[k];
    }
    g_alS2[n] = as;
    g_alD2[n] = ad;
}

/* -------- layer2 fused: per-lane online softmax, direct store -------------- */
__global__ __launch_bounds__(256)
void gat2_fused(float* __restrict__ dout, const float* __restrict__ b2) {
    const int d = (blockIdx.x * blockDim.x + threadIdx.x) >> 5;
    const int lane = threadIdx.x & 31;
    if (d >= N_NODES) return;
    const int rs = g_rowptr[d];
    const int deg = g_rowptr[d + 1] - rs;
    if (deg == 0) {
        if (lane == 0) {
#pragma unroll
            for (int k = 0; k < OUT_DIM; k++)
                dout[d * OUT_DIM + k] = b2[k];
        }
        return;
    }
    const float aD = g_alD2[d];

    float m = NEG_INF, den = 0.f;
    float acc[OUT_DIM] = {0, 0, 0, 0, 0};
    for (int j = lane; j < deg; j += 32) {
        int s = g_ssrc[rs + j];
        float lg = leaky(g_alS2[s] + aD);
        float mnew = fmaxf(m, lg);
        float sc = __expf(m - mnew);
        float ex = __expf(lg - mnew);
        den = den * sc + ex;
#pragma unroll
        for (int k = 0; k < OUT_DIM; k++)
            acc[k] = acc[k] * sc + ex * g_h2p[s * 8 + k];
        m = mnew;
    }
    float M = m;
#pragma unroll
    for (int o = 16; o; o >>= 1)
        M = fmaxf(M, __shfl_xor_sync(0xffffffffu, M, o));
    float sc = __expf(m - M);
    den *= sc;
#pragma unroll
    for (int k = 0; k < OUT_DIM; k++) acc[k] *= sc;
#pragma unroll
    for (int o = 16; o; o >>= 1) {
        den += __shfl_xor_sync(0xffffffffu, den, o);
#pragma unroll
        for (int k = 0; k < OUT_DIM; k++)
            acc[k] += __shfl_xor_sync(0xffffffffu, acc[k], o);
    }
    if (lane == 0) {
        const float inv = 1.0f / (den + EPS);
#pragma unroll
        for (int k = 0; k < OUT_DIM; k++)
            dout[d * OUT_DIM + k] = acc[k] * inv + b2[k];
    }
}

/* ---------------- launch --------------------------------------------------- */
extern "C" void kernel_launch(void* const* d_in, const int* in_sizes, int n_in,
                              void* d_out, int out_size) {
    const float* x   = (const float*)d_in[0];
    const int*   ei  = (const int*)  d_in[1];
    const float* W1  = (const float*)d_in[2];
    const float* aS1 = (const float*)d_in[3];
    const float* aD1 = (const float*)d_in[4];
    const float* b1  = (const float*)d_in[5];
    const float* W2  = (const float*)d_in[6];
    const float* aS2 = (const float*)d_in[7];
    const float* aD2 = (const float*)d_in[8];
    const float* b2  = (const float*)d_in[9];
    float*       out = (float*)d_out;

    const int* src = ei;
    const int* dst = ei + N_EDGES;

    static bool attr_set = false;
    if (!attr_set) {
        cudaFuncSetAttribute(gemm_mma_kernel,
                             cudaFuncAttributeMaxDynamicSharedMemorySize, GEMM_SMEM);
        attr_set = true;
    }

    split_x_kernel<<<(unsigned)(((size_t)N_PAD * IN_DIM / 4 + 255) / 256), 256>>>(x);
    split_w_kernel<<<(F1 * IN_DIM + 255) / 256, 256>>>(W1);
    count_kernel<<<(N_EDGES + 255) / 256, 256>>>(dst);
    scan1_kernel<<<SCAN_NBLK, 1024>>>();
    scan2_kernel<<<1, 32>>>();
    scan3_kernel<<<(N_NODES + 255) / 256, 256>>>();
    scatter_kernel<<<(N_EDGES + 255) / 256, 256>>>(src, dst);

    gemm_mma_kernel<<<dim3(F1 / 128, N_PAD / 128), 256, GEMM_SMEM>>>(aS1, aD1);

    gat1_fused<<<(N_NODES * HEADS * 32 + 255) / 256, 256>>>(b1, W2);
    alpha2_kernel<<<(N_NODES + 255) / 256, 256>>>(aS2, aD2);
    gat2_fused<<<(N_NODES * 32 + 255) / 256, 256>>>(out, b2);
}

// round 9
// speedup vs baseline: 4.2195x; 1.0804x over previous
#include <cuda_runtime.h>
#include <cuda_bf16.h>
#include <math.h>
#include <stdint.h>

#define N_NODES 50000
#define N_PAD   50048            /* 391 * 128 */
#define N_EDGES 800000
#define IN_DIM  384
#define HID     128
#define HEADS   4
#define OUT_DIM 5
#define F1      (HEADS * HID)    /* 512 */
#define EPS     1e-16f
#define NEG_SLOPE 0.2f
#define KC      64               /* K per chunk */
#define NCHUNK  18               /* 3 terms * 384/64 */
#define NEG_INF __int_as_float(0xff800000)
#define SCAN_NBLK ((N_NODES + 1023) / 1024)   /* 49 */

/* ---------------- scratch (device globals; no allocations allowed) -------- */
__device__ float g_h1  [(size_t)N_NODES * F1];     /* 102.4MB, L2-resident */
__device__ float g_alS1[N_NODES * HEADS];
__device__ float g_alD1[N_NODES * HEADS];
__device__ float g_h2p [N_NODES * 8];              /* padded h2 [N,8] */
__device__ float g_alS2[N_NODES];
__device__ float g_alD2[N_NODES];
/* CSR by destination */
__device__ int g_cnt   [N_NODES];
__device__ int g_rowptr[N_NODES + 1];
__device__ int g_cursor[N_NODES];
__device__ int g_ssrc  [N_EDGES];
__device__ int g_bsum  [SCAN_NBLK];
/* bf16 split operands for tensor-core GEMM1 */
__device__ __nv_bfloat16 g_xhi[(size_t)N_PAD * IN_DIM];
__device__ __nv_bfloat16 g_xlo[(size_t)N_PAD * IN_DIM];
__device__ __nv_bfloat16 g_wthi[(size_t)F1 * IN_DIM];   /* W1^T [512 x 384] */
__device__ __nv_bfloat16 g_wtlo[(size_t)F1 * IN_DIM];

/* ---------------- helpers ------------------------------------------------- */
__device__ __forceinline__ uint32_t smem_u32(const void* p) {
    uint32_t a;
    asm("{ .reg .u64 t; cvta.to.shared.u64 t, %1; cvt.u32.u64 %0, t; }"
        : "=r"(a) : "l"(p));
    return a;
}
__device__ __forceinline__ float leaky(float v) {
    return v > 0.0f ? v : NEG_SLOPE * v;
}
__device__ __forceinline__ void ldsm_x4(uint32_t* r, uint32_t addr) {
    asm volatile("ldmatrix.sync.aligned.m8n8.x4.shared.b16 {%0,%1,%2,%3}, [%4];"
                 : "=r"(r[0]), "=r"(r[1]), "=r"(r[2]), "=r"(r[3]) : "r"(addr));
}
__device__ __forceinline__ void mma_bf16(float* c, const uint32_t* a,
                                         const uint32_t* b) {
    asm volatile("mma.sync.aligned.m16n8k16.row.col.f32.bf16.bf16.f32 "
                 "{%0,%1,%2,%3}, {%4,%5,%6,%7}, {%8,%9}, {%0,%1,%2,%3};"
                 : "+f"(c[0]), "+f"(c[1]), "+f"(c[2]), "+f"(c[3])
                 : "r"(a[0]), "r"(a[1]), "r"(a[2]), "r"(a[3]),
                   "r"(b[0]), "r"(b[1]));
}
__device__ __forceinline__ void cp16(uint32_t saddr, const void* gaddr) {
    asm volatile("cp.async.cg.shared.global [%0], [%1], 16;"
                 :: "r"(saddr), "l"(gaddr));
}
#define CP_COMMIT() asm volatile("cp.async.commit_group;")
#define CP_WAIT0()  asm volatile("cp.async.wait_group 0;")

/* ---------------- split_x + init (fused) ----------------------------------- */
__global__ void split_x_kernel(const float* __restrict__ x) {
    size_t tid = (size_t)blockIdx.x * blockDim.x + threadIdx.x;
    /* fused init */
    if (tid < N_NODES * HEADS) { g_alS1[tid] = 0.0f; g_alD1[tid] = 0.0f; }
    if (tid < N_NODES) g_cnt[tid] = 0;

    size_t t = tid * 4;
    if (t >= (size_t)N_PAD * IN_DIM) return;
    float4 v = (t < (size_t)N_NODES * IN_DIM) ? *(const float4*)(x + t)
                                              : make_float4(0.f, 0.f, 0.f, 0.f);
    float vv[4] = {v.x, v.y, v.z, v.w};
    __nv_bfloat16 hi[4], lo[4];
#pragma unroll
    for (int i = 0; i < 4; i++) {
        hi[i] = __float2bfloat16(vv[i]);
        lo[i] = __float2bfloat16(vv[i] - __bfloat162float(hi[i]));
    }
    *(uint2*)(g_xhi + t) = *(uint2*)hi;
    *(uint2*)(g_xlo + t) = *(uint2*)lo;
}
__global__ void split_w_kernel(const float* __restrict__ W1) {
    int t = blockIdx.x * blockDim.x + threadIdx.x;
    if (t >= F1 * IN_DIM) return;
    int n = t / IN_DIM, k = t - n * IN_DIM;
    float v = W1[(size_t)k * F1 + n];
    __nv_bfloat16 hi = __float2bfloat16(v);
    g_wthi[t] = hi;
    g_wtlo[t] = __float2bfloat16(v - __bfloat162float(hi));
}

/* ---------------- CSR build (3-kernel parallel scan) ----------------------- */
__global__ void count_kernel(const int* __restrict__ dst) {
    int e = blockIdx.x * blockDim.x + threadIdx.x;
    if (e < N_EDGES) atomicAdd(&g_cnt[dst[e]], 1);
}
__global__ __launch_bounds__(1024)
void scan1_kernel() {                 /* per-block Hillis-Steele */
    __shared__ int s[1024];
    const int t = threadIdx.x;
    const int g = blockIdx.x * 1024 + t;
    const int v = (g < N_NODES) ? g_cnt[g] : 0;
    s[t] = v;
    __syncthreads();
#pragma unroll
    for (int off = 1; off < 1024; off <<= 1) {
        int x = (t >= off) ? s[t - off] : 0;
        __syncthreads();
        s[t] += x;
        __syncthreads();
    }
    if (g < N_NODES) g_rowptr[g] = s[t] - v;     /* exclusive partial */
    if (t == 1023) g_bsum[blockIdx.x] = s[1023];
}
__global__ void scan2_kernel() {      /* tiny serial scan of 49 block sums */
    if (threadIdx.x == 0) {
        int run = 0;
#pragma unroll 1
        for (int i = 0; i < SCAN_NBLK; i++) {
            int v = g_bsum[i];
            g_bsum[i] = run;
            run += v;
        }
        g_rowptr[N_NODES] = run;
    }
}
__global__ void scan3_kernel() {      /* add block offsets, fill cursor */
    int g = blockIdx.x * blockDim.x + threadIdx.x;
    if (g < N_NODES) {
        int v = g_rowptr[g] + g_bsum[g >> 10];
        g_rowptr[g] = v;
        g_cursor[g] = v;
    }
}
__global__ void scatter_kernel(const int* __restrict__ src,
                               const int* __restrict__ dst) {
    int e = blockIdx.x * blockDim.x + threadIdx.x;
    if (e >= N_EDGES) return;
    int p = atomicAdd(&g_cursor[dst[e]], 1);
    g_ssrc[p] = src[e];
}

/* ------- GEMM1 via mma.sync bf16x3, cp.async double-buffer ----------------- */
#define GEMM_SMEM 65536

__global__ __launch_bounds__(256, 2)
void gemm_mma_kernel(const float* __restrict__ aSrc,
                     const float* __restrict__ aDst) {
    extern __shared__ char smem[];
    const uint32_t sb = smem_u32(smem);
    const int tid = threadIdx.x, lane = tid & 31, wid = tid >> 5;
    const int wM = (wid & 3) * 32, wN = (wid >> 2) * 64;
    const size_t bm = (size_t)blockIdx.y * 128;
    const int bn0 = blockIdx.x * 128;

    float acc[2][8][4];
#pragma unroll
    for (int i = 0; i < 2; i++)
#pragma unroll
        for (int j = 0; j < 8; j++)
#pragma unroll
            for (int q = 0; q < 4; q++) acc[i][j][q] = 0.0f;

    auto issue = [&](int ch, int buf) {
        const int term = ch / 6, k0 = (ch % 6) * KC;
        const __nv_bfloat16* Ag = (term < 2) ? g_xhi : g_xlo;
        const __nv_bfloat16* Bg = (term == 1) ? g_wtlo : g_wthi;
        const uint32_t base = sb + buf * 32768;
#pragma unroll
        for (int l = 0; l < 4; l++) {
            int i = tid + l * 256;
            int r = i >> 3, c = i & 7;
            uint32_t off = r * 128 + ((c ^ (r & 7)) << 4);
            cp16(base + off, Ag + (bm + r) * IN_DIM + k0 + c * 8);
            cp16(base + 16384 + off, Bg + (size_t)(bn0 + r) * IN_DIM + k0 + c * 8);
        }
        CP_COMMIT();
    };

    issue(0, 0);

    for (int ch = 0; ch < NCHUNK; ch++) {
        CP_WAIT0();
        __syncthreads();
        if (ch + 1 < NCHUNK) issue(ch + 1, (ch + 1) & 1);
        const uint32_t sbA = sb + (ch & 1) * 32768;
        const uint32_t sbB = sbA + 16384;
#pragma unroll
        for (int k16 = 0; k16 < 4; k16++) {
            uint32_t a[2][4];
#pragma unroll
            for (int am = 0; am < 2; am++) {
                int r = wM + am * 16 + (lane & 15);
                int c = k16 * 2 + (lane >> 4);
                ldsm_x4(a[am], sbA + r * 128 + ((c ^ (r & 7)) << 4));
            }
#pragma unroll
            for (int bn2 = 0; bn2 < 4; bn2++) {
                int n = wN + bn2 * 16 + ((lane >> 4) << 3) + (lane & 7);
                int c = k16 * 2 + ((lane >> 3) & 1);
                uint32_t b[4];
                ldsm_x4(b, sbB + n * 128 + ((c ^ (n & 7)) << 4));
                mma_bf16(acc[0][bn2 * 2], a[0], b);
                mma_bf16(acc[1][bn2 * 2], a[1], b);
                mma_bf16(acc[0][bn2 * 2 + 1], a[0], b + 2);
                mma_bf16(acc[1][bn2 * 2 + 1], a[1], b + 2);
            }
        }
    }

    /* epilogue: write h1 + fused alpha1 partial dot products */
    const int qr = lane >> 2, qc = (lane & 3) * 2;
    const int hh = bn0 >> 7;
    float sA[4] = {0, 0, 0, 0}, sD[4] = {0, 0, 0, 0};

#pragma unroll
    for (int am = 0; am < 2; am++) {
        size_t r0 = bm + wM + am * 16 + qr;
#pragma unroll
        for (int half = 0; half < 2; half++) {
            size_t rr = r0 + half * 8;
            if (rr < N_NODES) {
                float* dstp = g_h1 + rr * F1 + bn0 + wN + qc;
#pragma unroll
                for (int bn = 0; bn < 8; bn++) {
                    float v0 = acc[am][bn][half * 2];
                    float v1 = acc[am][bn][half * 2 + 1];
                    *(float2*)(dstp + bn * 8) = make_float2(v0, v1);
                    const int c0 = bn0 + wN + bn * 8 + qc;
                    sA[am * 2 + half] += v0 * __ldg(aSrc + c0) + v1 * __ldg(aSrc + c0 + 1);
                    sD[am * 2 + half] += v0 * __ldg(aDst + c0) + v1 * __ldg(aDst + c0 + 1);
                }
            }
        }
    }
#pragma unroll
    for (int i = 0; i < 4; i++) {
#pragma unroll
        for (int o = 1; o <= 2; o <<= 1) {
            sA[i] += __shfl_xor_sync(0xffffffffu, sA[i], o);
            sD[i] += __shfl_xor_sync(0xffffffffu, sD[i], o);
        }
    }
    if ((lane & 3) == 0) {
#pragma unroll
        for (int am = 0; am < 2; am++)
#pragma unroll
            for (int half = 0; half < 2; half++) {
                size_t rr = bm + wM + am * 16 + half * 8 + qr;
                if (rr < N_NODES) {
                    atomicAdd(&g_alS1[rr * HEADS + hh], sA[am * 2 + half]);
                    atomicAdd(&g_alD1[rr * HEADS + hh], sD[am * 2 + half]);
                }
            }
    }
}

/* -------- layer1 fused: one warp per dst, ALL 4 heads ----------------------
   online softmax + aggregate + norm + bias + elu + W2 GEMV + alpha2.
   Plain stores to h2p/alS2/alD2 (warp owns dst — no atomics).              */
__global__ __launch_bounds__(256)
void gat1_fused(const float* __restrict__ b1, const float* __restrict__ W2,
                const float* __restrict__ a_s2, const float* __restrict__ a_d2) {
    const int d = (blockIdx.x * blockDim.x + threadIdx.x) >> 5;
    const int lane = threadIdx.x & 31;
    if (d >= N_NODES) return;
    const int rs = g_rowptr[d];
    const int deg = g_rowptr[d + 1] - rs;
    const float4 aD4 = *(const float4*)&g_alD1[d * HEADS];
    const float aD[4] = {aD4.x, aD4.y, aD4.z, aD4.w};

    float m[4] = {NEG_INF, NEG_INF, NEG_INF, NEG_INF};
    float den[4] = {0, 0, 0, 0};
    float acc[4][4] = {};

    for (int base = 0; base < deg; base += 32) {
        const bool act = base + lane < deg;
        int s = 0;
        float lg[4] = {NEG_INF, NEG_INF, NEG_INF, NEG_INF};
        if (act) {
            s = g_ssrc[rs + base + lane];
            float4 a4 = *(const float4*)&g_alS1[s * HEADS];
            lg[0] = leaky(a4.x + aD[0]);
            lg[1] = leaky(a4.y + aD[1]);
            lg[2] = leaky(a4.z + aD[2]);
            lg[3] = leaky(a4.w + aD[3]);
        }
        float ex[4];
#pragma unroll
        for (int h = 0; h < 4; h++) {
            float bmx = lg[h];
#pragma unroll
            for (int o = 16; o; o >>= 1)
                bmx = fmaxf(bmx, __shfl_xor_sync(0xffffffffu, bmx, o));
            const float mnew = fmaxf(m[h], bmx);
            const float sc = __expf(m[h] - mnew);    /* first batch: 0 */
            den[h] *= sc;
            acc[h][0] *= sc; acc[h][1] *= sc; acc[h][2] *= sc; acc[h][3] *= sc;
            ex[h] = act ? __expf(lg[h] - mnew) : 0.f;
            den[h] += ex[h];
            m[h] = mnew;
        }
        const int lim = min(32, deg - base);
        for (int jj = 0; jj < lim; jj++) {
            const int sj = __shfl_sync(0xffffffffu, s, jj);
            const float w0 = __shfl_sync(0xffffffffu, ex[0], jj);
            const float w1 = __shfl_sync(0xffffffffu, ex[1], jj);
            const float w2 = __shfl_sync(0xffffffffu, ex[2], jj);
            const float w3 = __shfl_sync(0xffffffffu, ex[3], jj);
            const float* row = g_h1 + (size_t)sj * F1 + lane * 4;
            const float4 v0 = *(const float4*)(row);
            const float4 v1 = *(const float4*)(row + HID);
            const float4 v2 = *(const float4*)(row + 2 * HID);
            const float4 v3 = *(const float4*)(row + 3 * HID);
            acc[0][0] += w0 * v0.x; acc[0][1] += w0 * v0.y;
            acc[0][2] += w0 * v0.z; acc[0][3] += w0 * v0.w;
            acc[1][0] += w1 * v1.x; acc[1][1] += w1 * v1.y;
            acc[1][2] += w1 * v1.z; acc[1][3] += w1 * v1.w;
            acc[2][0] += w2 * v2.x; acc[2][1] += w2 * v2.y;
            acc[2][2] += w2 * v2.z; acc[2][3] += w2 * v2.w;
            acc[3][0] += w3 * v3.x; acc[3][1] += w3 * v3.y;
            acc[3][2] += w3 * v3.z; acc[3][3] += w3 * v3.w;
        }
    }
    float inv[4];
#pragma unroll
    for (int h = 0; h < 4; h++) {
        float dn = den[h];
#pragma unroll
        for (int o = 16; o; o >>= 1)
            dn += __shfl_xor_sync(0xffffffffu, dn, o);
        inv[h] = 1.0f / (dn + EPS);
    }

    /* normalize + bias + elu + W2 GEMV (512 -> 5) */
    float p[OUT_DIM] = {0, 0, 0, 0, 0};
#pragma unroll
    for (int h = 0; h < 4; h++) {
#pragma unroll
        for (int q = 0; q < 4; q++) {
            const int c = h * HID + lane * 4 + q;
            float val = acc[h][q] * inv[h] + b1[c];
            val = val > 0.0f ? val : expm1f(val);
            const float* wr = W2 + c * OUT_DIM;
#pragma unroll
            for (int k = 0; k < OUT_DIM; k++) p[k] += val * wr[k];
        }
    }
#pragma unroll
    for (int k = 0; k < OUT_DIM; k++) {
#pragma unroll
        for (int o = 16; o; o >>= 1)
            p[k] += __shfl_xor_sync(0xffffffffu, p[k], o);
    }
    if (lane == 0) {
        float as = 0.f, ad = 0.f;
#pragma unroll
        for (int k = 0; k < OUT_DIM; k++) {
            g_h2p[d * 8 + k] = p[k];
            as += p[k] * a_s2[k];
            ad += p[k] * a_d2[k];
        }
        g_alS2[d] = as;
        g_alD2[d] = ad;
    }
}

/* -------- layer2 fused: per-lane online softmax, direct store -------------- */
__global__ __launch_bounds__(256)
void gat2_fused(float* __restrict__ dout, const float* __restrict__ b2) {
    const int d = (blockIdx.x * blockDim.x + threadIdx.x) >> 5;
    const int lane = threadIdx.x & 31;
    if (d >= N_NODES) return;
    const int rs = g_rowptr[d];
    const int deg = g_rowptr[d + 1] - rs;
    if (deg == 0) {
        if (lane == 0) {
#pragma unroll
            for (int k = 0; k < OUT_DIM; k++)
                dout[d * OUT_DIM + k] = b2[k];
        }
        return;
    }
    const float aD = g_alD2[d];

    float m = NEG_INF, den = 0.f;
    float acc[OUT_DIM] = {0, 0, 0, 0, 0};
    for (int j = lane; j < deg; j += 32) {
        int s = g_ssrc[rs + j];
        float lg = leaky(g_alS2[s] + aD);
        float mnew = fmaxf(m, lg);
        float sc = __expf(m - mnew);
        float ex = __expf(lg - mnew);
        den = den * sc + ex;
#pragma unroll
        for (int k = 0; k < OUT_DIM; k++)
            acc[k] = acc[k] * sc + ex * g_h2p[s * 8 + k];
        m = mnew;
    }
    float M = m;
#pragma unroll
    for (int o = 16; o; o >>= 1)
        M = fmaxf(M, __shfl_xor_sync(0xffffffffu, M, o));
    float sc = __expf(m - M);
    den *= sc;
#pragma unroll
    for (int k = 0; k < OUT_DIM; k++) acc[k] *= sc;
#pragma unroll
    for (int o = 16; o; o >>= 1) {
        den += __shfl_xor_sync(0xffffffffu, den, o);
#pragma unroll
        for (int k = 0; k < OUT_DIM; k++)
            acc[k] += __shfl_xor_sync(0xffffffffu, acc[k], o);
    }
    if (lane == 0) {
        const float inv = 1.0f / (den + EPS);
#pragma unroll
        for (int k = 0; k < OUT_DIM; k++)
            dout[d * OUT_DIM + k] = acc[k] * inv + b2[k];
    }
}

/* ---------------- launch --------------------------------------------------- */
extern "C" void kernel_launch(void* const* d_in, const int* in_sizes, int n_in,
                              void* d_out, int out_size) {
    const float* x   = (const float*)d_in[0];
    const int*   ei  = (const int*)  d_in[1];
    const float* W1  = (const float*)d_in[2];
    const float* aS1 = (const float*)d_in[3];
    const float* aD1 = (const float*)d_in[4];
    const float* b1  = (const float*)d_in[5];
    const float* W2  = (const float*)d_in[6];
    const float* aS2 = (const float*)d_in[7];
    const float* aD2 = (const float*)d_in[8];
    const float* b2  = (const float*)d_in[9];
    float*       out = (float*)d_out;

    const int* src = ei;
    const int* dst = ei + N_EDGES;

    static bool attr_set = false;
    if (!attr_set) {
        cudaFuncSetAttribute(gemm_mma_kernel,
                             cudaFuncAttributeMaxDynamicSharedMemorySize, GEMM_SMEM);
        attr_set = true;
    }

    split_x_kernel<<<(unsigned)(((size_t)N_PAD * IN_DIM / 4 + 255) / 256), 256>>>(x);
    split_w_kernel<<<(F1 * IN_DIM + 255) / 256, 256>>>(W1);
    count_kernel<<<(N_EDGES + 255) / 256, 256>>>(dst);
    scan1_kernel<<<SCAN_NBLK, 1024>>>();
    scan2_kernel<<<1, 32>>>();
    scan3_kernel<<<(N_NODES + 255) / 256, 256>>>();
    scatter_kernel<<<(N_EDGES + 255) / 256, 256>>>(src, dst);

    gemm_mma_kernel<<<dim3(F1 / 128, N_PAD / 128), 256, GEMM_SMEM>>>(aS1, aD1);

    gat1_fused<<<(N_NODES * 32 + 255) / 256, 256>>>(b1, W2, aS2, aD2);
    gat2_fused<<<(N_NODES * 32 + 255) / 256, 256>>>(out, b2);
}

// round 10
// speedup vs baseline: 4.5285x; 1.0732x over previous
#include <cuda_runtime.h>
#include <cuda_bf16.h>
#include <math.h>
#include <stdint.h>

#define N_NODES 50000
#define N_PAD   50048            /* 391 * 128 */
#define N_EDGES 800000
#define IN_DIM  384
#define HID     128
#define HEADS   4
#define OUT_DIM 5
#define F1      (HEADS * HID)    /* 512 */
#define EPS     1e-16f
#define NEG_SLOPE 0.2f
#define KC      64               /* K per chunk */
#define NCHUNK  18               /* 3 terms * 384/64 */
#define NEG_INF __int_as_float(0xff800000)
#define SCAN_NBLK ((N_NODES + 1023) / 1024)   /* 49 */

/* ---------------- scratch (device globals; no allocations allowed) -------- */
__device__ float g_h1  [(size_t)N_NODES * F1];     /* 102.4MB, L2-resident */
__device__ float g_alS1[N_NODES * HEADS];
__device__ float g_alD1[N_NODES * HEADS];
__device__ float g_h2p [N_NODES * 8];              /* padded h2 [N,8] */
__device__ float g_alS2[N_NODES];
__device__ float g_alD2[N_NODES];
/* CSR by destination */
__device__ int g_cnt   [N_NODES];
__device__ int g_rowptr[N_NODES + 1];
__device__ int g_cursor[N_NODES];
__device__ int g_ssrc  [N_EDGES];
__device__ int g_bsum  [SCAN_NBLK];
/* bf16 split operands for tensor-core GEMM1 */
__device__ __nv_bfloat16 g_xhi[(size_t)N_PAD * IN_DIM];
__device__ __nv_bfloat16 g_xlo[(size_t)N_PAD * IN_DIM];
__device__ __nv_bfloat16 g_wthi[(size_t)F1 * IN_DIM];   /* W1^T [512 x 384] */
__device__ __nv_bfloat16 g_wtlo[(size_t)F1 * IN_DIM];

/* ---------------- helpers ------------------------------------------------- */
__device__ __forceinline__ uint32_t smem_u32(const void* p) {
    uint32_t a;
    asm("{ .reg .u64 t; cvta.to.shared.u64 t, %1; cvt.u32.u64 %0, t; }"
        : "=r"(a) : "l"(p));
    return a;
}
__device__ __forceinline__ float leaky(float v) {
    return v > 0.0f ? v : NEG_SLOPE * v;
}
__device__ __forceinline__ void ldsm_x4(uint32_t* r, uint32_t addr) {
    asm volatile("ldmatrix.sync.aligned.m8n8.x4.shared.b16 {%0,%1,%2,%3}, [%4];"
                 : "=r"(r[0]), "=r"(r[1]), "=r"(r[2]), "=r"(r[3]) : "r"(addr));
}
__device__ __forceinline__ void mma_bf16(float* c, const uint32_t* a,
                                         const uint32_t* b) {
    asm volatile("mma.sync.aligned.m16n8k16.row.col.f32.bf16.bf16.f32 "
                 "{%0,%1,%2,%3}, {%4,%5,%6,%7}, {%8,%9}, {%0,%1,%2,%3};"
                 : "+f"(c[0]), "+f"(c[1]), "+f"(c[2]), "+f"(c[3])
                 : "r"(a[0]), "r"(a[1]), "r"(a[2]), "r"(a[3]),
                   "r"(b[0]), "r"(b[1]));
}
__device__ __forceinline__ void cp16(uint32_t saddr, const void* gaddr) {
    asm volatile("cp.async.cg.shared.global [%0], [%1], 16;"
                 :: "r"(saddr), "l"(gaddr));
}
#define CP_COMMIT() asm volatile("cp.async.commit_group;")
#define CP_WAIT0()  asm volatile("cp.async.wait_group 0;")
#define CP_WAIT1()  asm volatile("cp.async.wait_group 1;")

/* ---------------- split_x + init (fused) ----------------------------------- */
__global__ void split_x_kernel(const float* __restrict__ x) {
    size_t tid = (size_t)blockIdx.x * blockDim.x + threadIdx.x;
    if (tid < N_NODES * HEADS) { g_alS1[tid] = 0.0f; g_alD1[tid] = 0.0f; }

    size_t t = tid * 4;
    if (t >= (size_t)N_PAD * IN_DIM) return;
    float4 v = (t < (size_t)N_NODES * IN_DIM) ? *(const float4*)(x + t)
                                              : make_float4(0.f, 0.f, 0.f, 0.f);
    float vv[4] = {v.x, v.y, v.z, v.w};
    __nv_bfloat16 hi[4], lo[4];
#pragma unroll
    for (int i = 0; i < 4; i++) {
        hi[i] = __float2bfloat16(vv[i]);
        lo[i] = __float2bfloat16(vv[i] - __bfloat162float(hi[i]));
    }
    *(uint2*)(g_xhi + t) = *(uint2*)hi;
    *(uint2*)(g_xlo + t) = *(uint2*)lo;
}
__global__ void split_w_kernel(const float* __restrict__ W1) {
    int t = blockIdx.x * blockDim.x + threadIdx.x;
    if (t >= F1 * IN_DIM) return;
    int n = t / IN_DIM, k = t - n * IN_DIM;
    float v = W1[(size_t)k * F1 + n];
    __nv_bfloat16 hi = __float2bfloat16(v);
    g_wthi[t] = hi;
    g_wtlo[t] = __float2bfloat16(v - __bfloat162float(hi));
}

/* ---------------- CSR build (stream B) ------------------------------------- */
__global__ void zero_cnt_kernel() {
    int t = blockIdx.x * blockDim.x + threadIdx.x;
    if (t < N_NODES) g_cnt[t] = 0;
}
__global__ void count_kernel(const int* __restrict__ dst) {
    int e = blockIdx.x * blockDim.x + threadIdx.x;
    if (e < N_EDGES) atomicAdd(&g_cnt[dst[e]], 1);
}
__global__ __launch_bounds__(1024)
void scan1_kernel() {                 /* per-block Hillis-Steele */
    __shared__ int s[1024];
    const int t = threadIdx.x;
    const int g = blockIdx.x * 1024 + t;
    const int v = (g < N_NODES) ? g_cnt[g] : 0;
    s[t] = v;
    __syncthreads();
#pragma unroll
    for (int off = 1; off < 1024; off <<= 1) {
        int x = (t >= off) ? s[t - off] : 0;
        __syncthreads();
        s[t] += x;
        __syncthreads();
    }
    if (g < N_NODES) g_rowptr[g] = s[t] - v;     /* exclusive partial */
    if (t == 1023) g_bsum[blockIdx.x] = s[1023];
}
__global__ void scan2_kernel() {      /* tiny serial scan of 49 block sums */
    if (threadIdx.x == 0) {
        int run = 0;
#pragma unroll 1
        for (int i = 0; i < SCAN_NBLK; i++) {
            int v = g_bsum[i];
            g_bsum[i] = run;
            run += v;
        }
        g_rowptr[N_NODES] = run;
    }
}
__global__ void scan3_kernel() {      /* add block offsets, fill cursor */
    int g = blockIdx.x * blockDim.x + threadIdx.x;
    if (g < N_NODES) {
        int v = g_rowptr[g] + g_bsum[g >> 10];
        g_rowptr[g] = v;
        g_cursor[g] = v;
    }
}
__global__ void scatter_kernel(const int* __restrict__ src,
                               const int* __restrict__ dst) {
    int e = blockIdx.x * blockDim.x + threadIdx.x;
    if (e >= N_EDGES) return;
    int p = atomicAdd(&g_cursor[dst[e]], 1);
    g_ssrc[p] = src[e];
}

/* ------- GEMM1 via mma.sync bf16x3, cp.async 3-stage pipeline -------------- */
#define GEMM_SMEM (3 * 32768)

__global__ __launch_bounds__(256, 2)
void gemm_mma_kernel(const float* __restrict__ aSrc,
                     const float* __restrict__ aDst) {
    extern __shared__ char smem[];
    const uint32_t sb = smem_u32(smem);
    const int tid = threadIdx.x, lane = tid & 31, wid = tid >> 5;
    const int wM = (wid & 3) * 32, wN = (wid >> 2) * 64;
    const size_t bm = (size_t)blockIdx.y * 128;
    const int bn0 = blockIdx.x * 128;

    float acc[2][8][4];
#pragma unroll
    for (int i = 0; i < 2; i++)
#pragma unroll
        for (int j = 0; j < 8; j++)
#pragma unroll
            for (int q = 0; q < 4; q++) acc[i][j][q] = 0.0f;

    auto issue = [&](int ch, int buf) {
        const int term = ch / 6, k0 = (ch % 6) * KC;
        const __nv_bfloat16* Ag = (term < 2) ? g_xhi : g_xlo;
        const __nv_bfloat16* Bg = (term == 1) ? g_wtlo : g_wthi;
        const uint32_t base = sb + buf * 32768;
#pragma unroll
        for (int l = 0; l < 4; l++) {
            int i = tid + l * 256;
            int r = i >> 3, c = i & 7;
            uint32_t off = r * 128 + ((c ^ (r & 7)) << 4);
            cp16(base + off, Ag + (bm + r) * IN_DIM + k0 + c * 8);
            cp16(base + 16384 + off, Bg + (size_t)(bn0 + r) * IN_DIM + k0 + c * 8);
        }
        CP_COMMIT();
    };

    issue(0, 0);
    issue(1, 1);

    for (int ch = 0; ch < NCHUNK; ch++) {
        if (ch + 1 < NCHUNK) CP_WAIT1(); else CP_WAIT0();
        __syncthreads();
        if (ch + 2 < NCHUNK) issue(ch + 2, (ch + 2) % 3);
        const uint32_t sbA = sb + (ch % 3) * 32768;
        const uint32_t sbB = sbA + 16384;
#pragma unroll
        for (int k16 = 0; k16 < 4; k16++) {
            uint32_t a[2][4];
#pragma unroll
            for (int am = 0; am < 2; am++) {
                int r = wM + am * 16 + (lane & 15);
                int c = k16 * 2 + (lane >> 4);
                ldsm_x4(a[am], sbA + r * 128 + ((c ^ (r & 7)) << 4));
            }
#pragma unroll
            for (int bn2 = 0; bn2 < 4; bn2++) {
                int n = wN + bn2 * 16 + ((lane >> 4) << 3) + (lane & 7);
                int c = k16 * 2 + ((lane >> 3) & 1);
                uint32_t b[4];
                ldsm_x4(b, sbB + n * 128 + ((c ^ (n & 7)) << 4));
                mma_bf16(acc[0][bn2 * 2], a[0], b);
                mma_bf16(acc[1][bn2 * 2], a[1], b);
                mma_bf16(acc[0][bn2 * 2 + 1], a[0], b + 2);
                mma_bf16(acc[1][bn2 * 2 + 1], a[1], b + 2);
            }
        }
    }

    /* epilogue: write h1 + fused alpha1 partial dot products */
    const int qr = lane >> 2, qc = (lane & 3) * 2;
    const int hh = bn0 >> 7;
    float sA[4] = {0, 0, 0, 0}, sD[4] = {0, 0, 0, 0};

#pragma unroll
    for (int am = 0; am < 2; am++) {
        size_t r0 = bm + wM + am * 16 + qr;
#pragma unroll
        for (int half = 0; half < 2; half++) {
            size_t rr = r0 + half * 8;
            if (rr < N_NODES) {
                float* dstp = g_h1 + rr * F1 + bn0 + wN + qc;
#pragma unroll
                for (int bn = 0; bn < 8; bn++) {
                    float v0 = acc[am][bn][half * 2];
                    float v1 = acc[am][bn][half * 2 + 1];
                    *(float2*)(dstp + bn * 8) = make_float2(v0, v1);
                    const int c0 = bn0 + wN + bn * 8 + qc;
                    sA[am * 2 + half] += v0 * __ldg(aSrc + c0) + v1 * __ldg(aSrc + c0 + 1);
                    sD[am * 2 + half] += v0 * __ldg(aDst + c0) + v1 * __ldg(aDst + c0 + 1);
                }
            }
        }
    }
#pragma unroll
    for (int i = 0; i < 4; i++) {
#pragma unroll
        for (int o = 1; o <= 2; o <<= 1) {
            sA[i] += __shfl_xor_sync(0xffffffffu, sA[i], o);
            sD[i] += __shfl_xor_sync(0xffffffffu, sD[i], o);
        }
    }
    if ((lane & 3) == 0) {
#pragma unroll
        for (int am = 0; am < 2; am++)
#pragma unroll
            for (int half = 0; half < 2; half++) {
                size_t rr = bm + wM + am * 16 + half * 8 + qr;
                if (rr < N_NODES) {
                    atomicAdd(&g_alS1[rr * HEADS + hh], sA[am * 2 + half]);
                    atomicAdd(&g_alD1[rr * HEADS + hh], sD[am * 2 + half]);
                }
            }
    }
}

/* -------- layer1 fused: one warp per dst, ALL 4 heads ---------------------- */
__global__ __launch_bounds__(256)
void gat1_fused(const float* __restrict__ b1, const float* __restrict__ W2,
                const float* __restrict__ a_s2, const float* __restrict__ a_d2) {
    const int d = (blockIdx.x * blockDim.x + threadIdx.x) >> 5;
    const int lane = threadIdx.x & 31;
    if (d >= N_NODES) return;
    const int rs = g_rowptr[d];
    const int deg = g_rowptr[d + 1] - rs;
    const float4 aD4 = *(const float4*)&g_alD1[d * HEADS];
    const float aD[4] = {aD4.x, aD4.y, aD4.z, aD4.w};

    float m[4] = {NEG_INF, NEG_INF, NEG_INF, NEG_INF};
    float den[4] = {0, 0, 0, 0};
    float acc[4][4] = {};

    for (int base = 0; base < deg; base += 32) {
        const bool act = base + lane < deg;
        int s = 0;
        float lg[4] = {NEG_INF, NEG_INF, NEG_INF, NEG_INF};
        if (act) {
            s = g_ssrc[rs + base + lane];
            float4 a4 = *(const float4*)&g_alS1[s * HEADS];
            lg[0] = leaky(a4.x + aD[0]);
            lg[1] = leaky(a4.y + aD[1]);
            lg[2] = leaky(a4.z + aD[2]);
            lg[3] = leaky(a4.w + aD[3]);
        }
        float ex[4];
#pragma unroll
        for (int h = 0; h < 4; h++) {
            float bmx = lg[h];
#pragma unroll
            for (int o = 16; o; o >>= 1)
                bmx = fmaxf(bmx, __shfl_xor_sync(0xffffffffu, bmx, o));
            const float mnew = fmaxf(m[h], bmx);
            const float sc = __expf(m[h] - mnew);
            den[h] *= sc;
            acc[h][0] *= sc; acc[h][1] *= sc; acc[h][2] *= sc; acc[h][3] *= sc;
            ex[h] = act ? __expf(lg[h] - mnew) : 0.f;
            den[h] += ex[h];
            m[h] = mnew;
        }
        const int lim = min(32, deg - base);
        for (int jj = 0; jj < lim; jj++) {
            const int sj = __shfl_sync(0xffffffffu, s, jj);
            const float w0 = __shfl_sync(0xffffffffu, ex[0], jj);
            const float w1 = __shfl_sync(0xffffffffu, ex[1], jj);
            const float w2 = __shfl_sync(0xffffffffu, ex[2], jj);
            const float w3 = __shfl_sync(0xffffffffu, ex[3], jj);
            const float* row = g_h1 + (size_t)sj * F1 + lane * 4;
            const float4 v0 = *(const float4*)(row);
            const float4 v1 = *(const float4*)(row + HID);
            const float4 v2 = *(const float4*)(row + 2 * HID);
            const float4 v3 = *(const float4*)(row + 3 * HID);
            acc[0][0] += w0 * v0.x; acc[0][1] += w0 * v0.y;
            acc[0][2] += w0 * v0.z; acc[0][3] += w0 * v0.w;
            acc[1][0] += w1 * v1.x; acc[1][1] += w1 * v1.y;
            acc[1][2] += w1 * v1.z; acc[1][3] += w1 * v1.w;
            acc[2][0] += w2 * v2.x; acc[2][1] += w2 * v2.y;
            acc[2][2] += w2 * v2.z; acc[2][3] += w2 * v2.w;
            acc[3][0] += w3 * v3.x; acc[3][1] += w3 * v3.y;
            acc[3][2] += w3 * v3.z; acc[3][3] += w3 * v3.w;
        }
    }
    float inv[4];
#pragma unroll
    for (int h = 0; h < 4; h++) {
        float dn = den[h];
#pragma unroll
        for (int o = 16; o; o >>= 1)
            dn += __shfl_xor_sync(0xffffffffu, dn, o);
        inv[h] = 1.0f / (dn + EPS);
    }

    float p[OUT_DIM] = {0, 0, 0, 0, 0};
#pragma unroll
    for (int h = 0; h < 4; h++) {
#pragma unroll
        for (int q = 0; q < 4; q++) {
            const int c = h * HID + lane * 4 + q;
            float val = acc[h][q] * inv[h] + b1[c];
            val = val > 0.0f ? val : expm1f(val);
            const float* wr = W2 + c * OUT_DIM;
#pragma unroll
            for (int k = 0; k < OUT_DIM; k++) p[k] += val * wr[k];
        }
    }
#pragma unroll
    for (int k = 0; k < OUT_DIM; k++) {
#pragma unroll
        for (int o = 16; o; o >>= 1)
            p[k] += __shfl_xor_sync(0xffffffffu, p[k], o);
    }
    if (lane == 0) {
        float as = 0.f, ad = 0.f;
#pragma unroll
        for (int k = 0; k < OUT_DIM; k++) {
            g_h2p[d * 8 + k] = p[k];
            as += p[k] * a_s2[k];
            ad += p[k] * a_d2[k];
        }
        g_alS2[d] = as;
        g_alD2[d] = ad;
    }
}

/* -------- layer2 fused: per-lane online softmax, direct store -------------- */
__global__ __launch_bounds__(256)
void gat2_fused(float* __restrict__ dout, const float* __restrict__ b2) {
    const int d = (blockIdx.x * blockDim.x + threadIdx.x) >> 5;
    const int lane = threadIdx.x & 31;
    if (d >= N_NODES) return;
    const int rs = g_rowptr[d];
    const int deg = g_rowptr[d + 1] - rs;
    if (deg == 0) {
        if (lane == 0) {
#pragma unroll
            for (int k = 0; k < OUT_DIM; k++)
                dout[d * OUT_DIM + k] = b2[k];
        }
        return;
    }
    const float aD = g_alD2[d];

    float m = NEG_INF, den = 0.f;
    float acc[OUT_DIM] = {0, 0, 0, 0, 0};
    for (int j = lane; j < deg; j += 32) {
        int s = g_ssrc[rs + j];
        float lg = leaky(g_alS2[s] + aD);
        float mnew = fmaxf(m, lg);
        float sc = __expf(m - mnew);
        float ex = __expf(lg - mnew);
        den = den * sc + ex;
#pragma unroll
        for (int k = 0; k < OUT_DIM; k++)
            acc[k] = acc[k] * sc + ex * g_h2p[s * 8 + k];
        m = mnew;
    }
    float M = m;
#pragma unroll
    for (int o = 16; o; o >>= 1)
        M = fmaxf(M, __shfl_xor_sync(0xffffffffu, M, o));
    float sc = __expf(m - M);
    den *= sc;
#pragma unroll
    for (int k = 0; k < OUT_DIM; k++) acc[k] *= sc;
#pragma unroll
    for (int o = 16; o; o >>= 1) {
        den += __shfl_xor_sync(0xffffffffu, den, o);
#pragma unroll
        for (int k = 0; k < OUT_DIM; k++)
            acc[k] += __shfl_xor_sync(0xffffffffu, acc[k], o);
    }
    if (lane == 0) {
        const float inv = 1.0f / (den + EPS);
#pragma unroll
        for (int k = 0; k < OUT_DIM; k++)
            dout[d * OUT_DIM + k] = acc[k] * inv + b2[k];
    }
}

/* ---------------- launch --------------------------------------------------- */
extern "C" void kernel_launch(void* const* d_in, const int* in_sizes, int n_in,
                              void* d_out, int out_size) {
    const float* x   = (const float*)d_in[0];
    const int*   ei  = (const int*)  d_in[1];
    const float* W1  = (const float*)d_in[2];
    const float* aS1 = (const float*)d_in[3];
    const float* aD1 = (const float*)d_in[4];
    const float* b1  = (const float*)d_in[5];
    const float* W2  = (const float*)d_in[6];
    const float* aS2 = (const float*)d_in[7];
    const float* aD2 = (const float*)d_in[8];
    const float* b2  = (const float*)d_in[9];
    float*       out = (float*)d_out;

    const int* src = ei;
    const int* dst = ei + N_EDGES;

    static bool init_done = false;
    static cudaStream_t sB;
    static cudaEvent_t evFork, evJoin;
    if (!init_done) {
        cudaFuncSetAttribute(gemm_mma_kernel,
                             cudaFuncAttributeMaxDynamicSharedMemorySize, GEMM_SMEM);
        cudaStreamCreateWithFlags(&sB, cudaStreamNonBlocking);
        cudaEventCreateWithFlags(&evFork, cudaEventDisableTiming);
        cudaEventCreateWithFlags(&evJoin, cudaEventDisableTiming);
        init_done = true;
    }

    /* fork: CSR build on stream B, overlapped with split + GEMM on stream 0 */
    cudaEventRecord(evFork, 0);
    cudaStreamWaitEvent(sB, evFork, 0);

    zero_cnt_kernel<<<(N_NODES + 255) / 256, 256, 0, sB>>>();
    count_kernel<<<(N_EDGES + 255) / 256, 256, 0, sB>>>(dst);
    scan1_kernel<<<SCAN_NBLK, 1024, 0, sB>>>();
    scan2_kernel<<<1, 32, 0, sB>>>();
    scan3_kernel<<<(N_NODES + 255) / 256, 256, 0, sB>>>();
    scatter_kernel<<<(N_EDGES + 255) / 256, 256, 0, sB>>>(src, dst);
    cudaEventRecord(evJoin, sB);

    split_x_kernel<<<(unsigned)(((size_t)N_PAD * IN_DIM / 4 + 255) / 256), 256>>>(x);
    split_w_kernel<<<(F1 * IN_DIM + 255) / 256, 256>>>(W1);
    gemm_mma_kernel<<<dim3(F1 / 128, N_PAD / 128), 256, GEMM_SMEM>>>(aS1, aD1);

    /* join: gat1 needs both the GEMM outputs and the CSR */
    cudaStreamWaitEvent(0, evJoin, 0);

    gat1_fused<<<(N_NODES * 32 + 255) / 256, 256>>>(b1, W2, aS2, aD2);
    gat2_fused<<<(N_NODES * 32 + 255) / 256, 256>>>(out, b2);
}